// round 12
// baseline (speedup 1.0000x reference)
#include <cuda_runtime.h>
#include <cstdint>
#include <math.h>

#define HH 48
#define WW 48
#define SP 2304
#define CC 192
#define BB 8
#define TOTAL 3538944

typedef unsigned long long u64;

// ---------------- scratch ----------------
__device__ float g_pad[BB*CC*2500];    // zero-bordered [b][c][50][50]
__device__ float g_pad2[BB*16*2600];   // zero-bordered [b][c][52][50] (attn out)
__device__ float g_wt[CC*1728];        // conv1 weights tap-major
__device__ float g_wtB[CC*1728];       // conv2 weights tap-major
__device__ float g_wt2[CC*160];        // out conv weights tap-major, K padded to 160
__device__ float g_h[TOTAL];
__device__ float g_xres[TOTAL];
__device__ float g_q[BB*16*SP];
__device__ float g_kv[BB*32*SP];
__device__ float g_mean[BB*32];
__device__ float g_rstd[BB*32];
__device__ float g_gbsum[BB*CC];

// ---------------- helpers ----------------
__device__ __forceinline__ float warp_red(float v) {
    #pragma unroll
    for (int o = 16; o > 0; o >>= 1) v += __shfl_down_sync(0xffffffffu, v, o);
    return v;
}
__device__ __forceinline__ uint32_t to_tf32(float f) {
    uint32_t r; asm("cvt.rna.tf32.f32 %0, %1;" : "=r"(r) : "f"(f)); return r;
}
__device__ __forceinline__ void mma_tf32(float c[4], const uint32_t a[4], const uint32_t b[2]) {
    asm volatile(
        "mma.sync.aligned.m16n8k8.row.col.f32.tf32.tf32.f32 "
        "{%0,%1,%2,%3}, {%4,%5,%6,%7}, {%8,%9}, {%0,%1,%2,%3};"
        : "+f"(c[0]), "+f"(c[1]), "+f"(c[2]), "+f"(c[3])
        : "r"(a[0]), "r"(a[1]), "r"(a[2]), "r"(a[3]), "r"(b[0]), "r"(b[1]));
}
__device__ __forceinline__ void ldsm_x4(uint32_t r[4], uint32_t addr) {
    asm volatile("ldmatrix.sync.aligned.m8n8.x4.shared.b16 {%0,%1,%2,%3}, [%4];"
        : "=r"(r[0]), "=r"(r[1]), "=r"(r[2]), "=r"(r[3]) : "r"(addr));
}
__device__ __forceinline__ uint32_t smaddr(const void* p) {
    return (uint32_t)__cvta_generic_to_shared(p);
}
__device__ __forceinline__ void cp4(uint32_t dst, const void* src) {
    asm volatile("cp.async.ca.shared.global [%0], [%1], 4;" :: "r"(dst), "l"(src));
}
__device__ __forceinline__ void cp16(uint32_t dst, const void* src) {
    asm volatile("cp.async.cg.shared.global [%0], [%1], 16;" :: "r"(dst), "l"(src));
}
#define CP_COMMIT() asm volatile("cp.async.commit_group;" ::: "memory")
#define CP_WAIT2()  asm volatile("cp.async.wait_group 2;" ::: "memory")

// ---------------- prep: affine + all 3 weight transposes in one launch ----------------
__global__ __launch_bounds__(256) void prep_kernel(const float* __restrict__ temb,
                                                   const float* __restrict__ aw,
                                                   const float* __restrict__ ab,
                                                   float* __restrict__ gbsum,
                                                   const float* __restrict__ w1,
                                                   const float* __restrict__ w2,
                                                   const float* __restrict__ w3,
                                                   float* __restrict__ o1,
                                                   float* __restrict__ o2,
                                                   float* __restrict__ o3) {
    int bx = blockIdx.x;
    int tid = threadIdx.x;
    if (bx < 8) {
        if (tid < 192) {
            __shared__ float t[192];
            t[tid] = temb[bx * 192 + tid];
            __syncthreads();
            float s = ab[tid] + ab[192 + tid];
            const float* wa = aw + tid * 192;
            const float* wb = aw + (192 + tid) * 192;
            for (int e = 0; e < 192; ++e) s = fmaf(t[e], wa[e] + wb[e], s);
            gbsum[bx * 192 + tid] = 0.5f * s;
        } else {
            __syncthreads();
        }
    } else if (bx < 8 + 1296) {
        int i = (bx - 8) * 256 + tid;
        if (i < CC * 1728) {
            int n = i / 1728;
            int k = i - n * 1728;
            int ci = k / 9;
            int tap = k - ci * 9;
            o1[n * 1728 + tap * 192 + ci] = w1[i];
        }
    } else if (bx < 8 + 2592) {
        int i = (bx - 8 - 1296) * 256 + tid;
        if (i < CC * 1728) {
            int n = i / 1728;
            int k = i - n * 1728;
            int ci = k / 9;
            int tap = k - ci * 9;
            o2[n * 1728 + tap * 192 + ci] = w2[i];
        }
    } else {
        int i = (bx - 8 - 2592) * 256 + tid;   // 108 blocks: full 192*144 coverage
        if (i < CC * 144) {
            int n = i / 144;
            int k = i - n * 144;
            int ci = k / 9;
            int tap = k - ci * 9;
            o3[n * 160 + tap * 16 + ci] = w3[i];
        }
    }
}

// ---------------- GroupNorm stats ----------------
__global__ __launch_bounds__(256) void gn_stats(const float* __restrict__ in,
                                                float* __restrict__ mean,
                                                float* __restrict__ rstd) {
    int bg = blockIdx.x;
    const float* base = in + (long)bg * 13824;
    float s = 0.f, s2 = 0.f;
    for (int i = threadIdx.x; i < 13824; i += 256) {
        float v = base[i];
        s += v; s2 = fmaf(v, v, s2);
    }
    __shared__ float shs[8], shs2[8];
    int w = threadIdx.x >> 5, l = threadIdx.x & 31;
    s = warp_red(s); s2 = warp_red(s2);
    if (l == 0) { shs[w] = s; shs2[w] = s2; }
    __syncthreads();
    if (w == 0) {
        s  = (l < 8) ? shs[l]  : 0.f;
        s2 = (l < 8) ? shs2[l] : 0.f;
        s = warp_red(s); s2 = warp_red(s2);
        if (l == 0) {
            float m = s * (1.f / 13824.f);
            float var = s2 * (1.f / 13824.f) - m * m;
            mean[bg] = m;
            rstd[bg] = rsqrtf(var + 1e-5f);
        }
    }
}

// ---------------- GroupNorm apply + swish -> padded [b][c][50][50] ----------------
__global__ __launch_bounds__(256) void gn_apply_pad(const float* __restrict__ in,
                                                    const float* __restrict__ mean,
                                                    const float* __restrict__ rstd,
                                                    const float* __restrict__ w,
                                                    const float* __restrict__ bb,
                                                    float* __restrict__ outpad) {
    int idx = blockIdx.x * 256 + threadIdx.x;
    int bc = idx / SP;
    int sp = idx - bc * SP;
    int b = bc / CC;
    int c = bc - b * CC;
    int sidx = b * 32 + c / 6;
    float y = (in[idx] - mean[sidx]) * rstd[sidx] * w[c] + bb[c];
    y = y / (1.f + __expf(-y));
    int py = sp / 48, px = sp - py * 48;
    outpad[(size_t)bc * 2500 + (py + 1) * 50 + (px + 1)] = y;
}

// ---------------- direct-shift TF32 mma conv (CIN=192, OC=192) --------------------
// R7/R10 compute & staging bodies EXACT; iterations paired: two stages per barrier
// (54 barriers instead of 108). Weight ring deepened to 8 so stages s..s+5 never
// alias a live buffer within one inter-barrier window.
#define WROW 20
#define WBUFSZ (192 * WROW)       // 3840 floats per weight stage
#define IBUFSZ (16 * 184)         // 2944 floats per input buffer
#define WRING 8
#define IOFF (WRING * WBUFSZ)
template<int EPI>
__global__ __launch_bounds__(256) void conv_mma(const float* __restrict__ pad,
                                                const float* __restrict__ wt,
                                                const float* __restrict__ bias,
                                                const float* __restrict__ extra,
                                                float* __restrict__ out) {
    extern __shared__ float sm[];

    const int mtile = blockIdx.x;       // 0..17
    const int b = blockIdx.y;
    const int tr = mtile / 3;           // row-tile 0..5 (8 rows)
    const int tcl = mtile - tr * 3;     // col-tile 0..2 (16 cols)
    const int tid = threadIdx.x;
    const int wid = tid >> 5;
    const int lane = tid & 31;
    const int g = lane >> 2;
    const int t = lane & 3;
    const int wm = wid & 3;             // 4 M tiles of 48 channels
    const int wn = wid >> 2;            // 2 N tiles of 64 positions

    const float* padb = pad + (size_t)b * CC * 2500;

    const uint32_t lane_a_off =
        ((uint32_t)((wm * 48 + (lane & 15)) * WROW + ((lane >> 4) << 2))) << 2;

    float acc[3][8][4];
    #pragma unroll
    for (int i = 0; i < 3; ++i)
        #pragma unroll
        for (int j = 0; j < 8; ++j)
            #pragma unroll
            for (int q = 0; q < 4; ++q) acc[i][j][q] = 0.f;

    auto stage = [&](int s) {
        int c = s / 9;
        int tap = s - c * 9;
        float* wbuf = sm + (s & (WRING - 1)) * WBUFSZ;
        #pragma unroll
        for (int it = 0; it < 3; ++it) {
            int idx = it * 256 + tid;
            int n = idx >> 2;
            int kq = (idx & 3) * 4;
            cp16(smaddr(&wbuf[n * WROW + kq]),
                 wt + (size_t)n * 1728 + tap * 192 + c * 16 + kq);
        }
        if (tap == 0) {
            float* ibuf = sm + IOFF + (c & 1) * IBUFSZ;
            #pragma unroll
            for (int it = 0; it < 12; ++it) {
                int idx = it * 256 + tid;
                if (idx < 2880) {
                    int ci = idx / 180;
                    int rem = idx - ci * 180;
                    int rr = rem / 18;
                    int cc2 = rem - rr * 18;
                    cp4(smaddr(&ibuf[ci * 184 + rr * 18 + cc2]),
                        padb + (size_t)(c * 16 + ci) * 2500
                             + (tr * 8 + rr) * 50 + tcl * 16 + cc2);
                }
            }
        }
    };

    auto compute = [&](int s) {
        const int c = s / 9;
        const int tap = s - c * 9;
        const int dy = tap / 3;
        const int dx = tap - dy * 3;
        const uint32_t wb_addr = smaddr(sm + (s & (WRING - 1)) * WBUFSZ) + lane_a_off;
        const float* ib = sm + IOFF + (c & 1) * IBUFSZ
                        + dy * 18 + dx + t * 184 + wn * 72 + g;
        #pragma unroll
        for (int ks = 0; ks < 2; ++ks) {
            const float* ibk = ib + ks * (8 * 184);
            uint32_t afr[3][4];
            #pragma unroll
            for (int i = 0; i < 3; ++i)
                ldsm_x4(afr[i], wb_addr + i * (16 * WROW * 4) + ks * 32);
            uint32_t bfr[8][2];
            #pragma unroll
            for (int j = 0; j < 8; ++j) {
                const float* a = ibk + (j >> 1) * 18 + (j & 1) * 8;
                bfr[j][0] = *(const uint32_t*)a;
                bfr[j][1] = *(const uint32_t*)(a + 4 * 184);
            }
            #pragma unroll
            for (int i = 0; i < 3; ++i)
                #pragma unroll
                for (int j = 0; j < 8; ++j)
                    mma_tf32(acc[i][j], afr[i], bfr[j]);
        }
    };

    stage(0); CP_COMMIT();
    stage(1); CP_COMMIT();
    stage(2); CP_COMMIT();
    stage(3); CP_COMMIT();

    for (int i = 0; i < 54; ++i) {
        CP_WAIT2();
        __syncthreads();
        const int s = 2 * i;
        compute(s);
        compute(s + 1);
        if (s + 4 < 108) stage(s + 4);
        CP_COMMIT();
        if (s + 5 < 108) stage(s + 5);
        CP_COMMIT();
    }

    // epilogue: tile position n -> (y,x); coalesced float2 stores
    #pragma unroll
    for (int i = 0; i < 3; ++i) {
        const int ch0 = wm * 48 + i * 16 + g;
        const int ch1 = ch0 + 8;
        const float bv0 = bias[ch0], bv1 = bias[ch1];
        float ga0 = 0.f, ga1 = 0.f;
        if (EPI == 0) { ga0 = extra[b * CC + ch0]; ga1 = extra[b * CC + ch1]; }
        #pragma unroll
        for (int j = 0; j < 8; ++j) {
            const int n = wn * 64 + j * 8 + 2 * t;
            const int yy = tr * 8 + (n >> 4);
            const int xx = tcl * 16 + (n & 15);
            long idx0 = (((long)b * CC + ch0) * 48 + yy) * 48 + xx;
            long idx1 = (((long)b * CC + ch1) * 48 + yy) * 48 + xx;
            float y0 = acc[i][j][0] + bv0;
            float y1 = acc[i][j][1] + bv0;
            float y2 = acc[i][j][2] + bv1;
            float y3 = acc[i][j][3] + bv1;
            if (EPI == 0) {
                y0 += ga0 * y0 + ga0; y1 += ga0 * y1 + ga0;
                y2 += ga1 * y2 + ga1; y3 += ga1 * y3 + ga1;
            } else {
                float2 e0 = *(const float2*)(extra + idx0);
                float2 e1 = *(const float2*)(extra + idx1);
                y0 += e0.x; y1 += e0.y; y2 += e1.x; y3 += e1.y;
            }
            *(float2*)(out + idx0) = make_float2(y0, y1);
            *(float2*)(out + idx1) = make_float2(y2, y3);
        }
    }
}

// ---------------- out conv: CIN=16 (K padded to 160), im2col pipeline ----------------
#define WST 36
#define ASZ (192 * WST)
#define BSZ (32 * 128)
#define STG (ASZ + BSZ)
__global__ __launch_bounds__(256) void conv_mma16(const float* __restrict__ pad2,
                                                  const float* __restrict__ wt,
                                                  const float* __restrict__ bias,
                                                  const float* __restrict__ extra,
                                                  float* __restrict__ out) {
    extern __shared__ float smf[];
    uint32_t* sm = (uint32_t*)smf;

    const int mtile = blockIdx.x;
    const int b = blockIdx.y;
    const int tid = threadIdx.x;
    const int wid = tid >> 5;
    const int lane = tid & 31;
    const int g = lane >> 2;
    const int t = lane & 3;
    const int wm = wid & 3;
    const int wn = wid >> 2;

    const int p = tid & 127;
    const int khalf = tid >> 7;
    const int pg = mtile * 128 + p;
    const int py = pg / 48;
    const int px = pg - py * 48;
    const float* padb = pad2 + (size_t)b * 16 * 2600;

    auto stage = [&](int c) {
        uint32_t* buf = sm + (c & 3) * STG;
        const int tap = 2 * c + khalf;
        const int dy = tap / 3;
        const int dx = tap - dy * 3;
        const float* bsrc = padb + (py + dy) * 50 + (px + dx);
        uint32_t* Bs = buf + ASZ;
        #pragma unroll
        for (int i = 0; i < 16; ++i) {
            int kk = khalf * 16 + i;
            cp4(smaddr(&Bs[kk * 128 + (p ^ ((kk & 3) * 8))]), bsrc + (size_t)i * 2600);
        }
        #pragma unroll
        for (int it = 0; it < 6; ++it) {
            int idx = it * 256 + tid;
            int n = idx >> 3;
            int kq = (idx & 7) * 4;
            cp16(smaddr(&buf[n * WST + kq]), wt + (size_t)n * 160 + c * 32 + kq);
        }
    };

    stage(0); CP_COMMIT();
    stage(1); CP_COMMIT();
    stage(2); CP_COMMIT();

    float acc[3][8][4];
    #pragma unroll
    for (int i = 0; i < 3; ++i)
        #pragma unroll
        for (int j = 0; j < 8; ++j)
            #pragma unroll
            for (int q = 0; q < 4; ++q) acc[i][j][q] = 0.f;

    for (int c = 0; c < 5; ++c) {
        CP_WAIT2();
        __syncthreads();
        const uint32_t* Wp = sm + (c & 3) * STG;
        const uint32_t* Ip = Wp + ASZ;
        #pragma unroll
        for (int ks = 0; ks < 4; ++ks) {
            const int kk0 = ks * 8;
            uint32_t afr[3][4];
            #pragma unroll
            for (int i = 0; i < 3; ++i) {
                int row = wm * 48 + i * 16 + g;
                afr[i][0] = Wp[row * WST + kk0 + t];
                afr[i][1] = Wp[(row + 8) * WST + kk0 + t];
                afr[i][2] = Wp[row * WST + kk0 + t + 4];
                afr[i][3] = Wp[(row + 8) * WST + kk0 + t + 4];
            }
            uint32_t bfr[8][2];
            #pragma unroll
            for (int j = 0; j < 8; ++j) {
                int pp = wn * 64 + j * 8 + g;
                int ppx = pp ^ (t * 8);
                bfr[j][0] = Ip[(kk0 + t) * 128 + ppx];
                bfr[j][1] = Ip[(kk0 + t + 4) * 128 + ppx];
            }
            #pragma unroll
            for (int i = 0; i < 3; ++i)
                #pragma unroll
                for (int j = 0; j < 8; ++j)
                    mma_tf32(acc[i][j], afr[i], bfr[j]);
        }
        if (c + 3 < 5) stage(c + 3);
        CP_COMMIT();
    }

    #pragma unroll
    for (int i = 0; i < 3; ++i) {
        const int ch0 = wm * 48 + i * 16 + g;
        const int ch1 = ch0 + 8;
        const float bv0 = bias[ch0], bv1 = bias[ch1];
        #pragma unroll
        for (int j = 0; j < 8; ++j) {
            const int pos = mtile * 128 + wn * 64 + j * 8 + 2 * t;
            long idx0 = ((long)b * CC + ch0) * SP + pos;
            long idx1 = ((long)b * CC + ch1) * SP + pos;
            float2 e0 = *(const float2*)(extra + idx0);
            float2 e1 = *(const float2*)(extra + idx1);
            *(float2*)(out + idx0) = make_float2(acc[i][j][0] + bv0 + e0.x,
                                                 acc[i][j][1] + bv0 + e0.y);
            *(float2*)(out + idx1) = make_float2(acc[i][j][2] + bv1 + e1.x,
                                                 acc[i][j][3] + bv1 + e1.y);
        }
    }
}

// ---------------- 1x1 conv: 128 threads / 128 positions, grid (18, B) ----------------
template<int CO>
__global__ __launch_bounds__(128) void conv1x1(const float* __restrict__ in,
                                               const float* __restrict__ wgt,
                                               float* __restrict__ out) {
    const int b = blockIdx.y;
    const int p0 = blockIdx.x * 128;
    const int tid = threadIdx.x;
    __shared__ float s_w[CO * 192];
    __shared__ float s_x[16 * 128];
    for (int i = tid; i < CO * 192; i += 128) s_w[i] = wgt[i];
    float acc[CO];
    #pragma unroll
    for (int co = 0; co < CO; ++co) acc[co] = 0.f;

    for (int c0 = 0; c0 < 192; c0 += 16) {
        __syncthreads();
        for (int i = tid; i < 16 * 128; i += 128) {
            int ci = i >> 7;
            int pp = i & 127;
            s_x[i] = in[((long)b * 192 + c0 + ci) * SP + p0 + pp];
        }
        __syncthreads();
        #pragma unroll
        for (int ci = 0; ci < 16; ++ci) {
            float xv = s_x[ci * 128 + tid];
            #pragma unroll
            for (int co = 0; co < CO; ++co)
                acc[co] = fmaf(s_w[co * 192 + c0 + ci], xv, acc[co]);
        }
    }
    #pragma unroll
    for (int co = 0; co < CO; ++co)
        out[((long)b * CO + co) * SP + p0 + tid] = acc[co];
}

// ---------------- MMA flash attention -> padded [b][16][52][50] ----------------
__global__ __launch_bounds__(256) void attn_mma(const float* __restrict__ q,
                                                const float* __restrict__ kv,
                                                float* __restrict__ pad2) {
    const int b = blockIdx.y;
    const int mtile = blockIdx.x;
    const int q0 = mtile * 128;
    const int tid = threadIdx.x;
    const int wid = tid >> 5;
    const int lane = tid & 31;
    const int g = lane >> 2;
    const int t = lane & 3;

    __shared__ float k_s[16 * 136];
    __shared__ float v_s[128 * 24];

    uint32_t qa[2][4];
    #pragma unroll
    for (int kd = 0; kd < 2; ++kd)
        #pragma unroll
        for (int j = 0; j < 4; ++j) {
            int row = wid * 16 + g + (j & 1) * 8;
            int d = kd * 8 + t + (j >> 1) * 4;
            float v = q[((long)b * 16 + d) * SP + q0 + row] * 0.25f;
            qa[kd][j] = to_tf32(v);
        }

    float m[2] = { -3.4e38f, -3.4e38f };
    float l[2] = { 0.f, 0.f };
    float acc_o[2][4];
    #pragma unroll
    for (int dn = 0; dn < 2; ++dn)
        #pragma unroll
        for (int j = 0; j < 4; ++j) acc_o[dn][j] = 0.f;

    const long kvb = (long)b * 32 * SP;
    for (int kb = 0; kb < 18; ++kb) {
        __syncthreads();
        const int key0 = kb * 128;
        #pragma unroll
        for (int it = 0; it < 8; ++it) {
            int idx = it * 256 + tid;
            int c = idx >> 7;
            int key = idx & 127;
            k_s[c * 136 + key] =
                __uint_as_float(to_tf32(kv[kvb + (long)c * SP + key0 + key]));
        }
        #pragma unroll
        for (int it = 0; it < 8; ++it) {
            int idx = it * 256 + tid;
            int d = idx >> 7;
            int key = idx & 127;
            int kp = key & 7;
            int kap = (kp & 1) ? (kp >> 1) + 4 : (kp >> 1);
            int slot = (key & ~7) | kap;
            v_s[slot * 24 + d] =
                __uint_as_float(to_tf32(kv[kvb + (long)(16 + d) * SP + key0 + key]));
        }
        __syncthreads();

        float s_fr[16][4];
        #pragma unroll
        for (int nt = 0; nt < 16; ++nt) {
            float c4[4] = { 0.f, 0.f, 0.f, 0.f };
            #pragma unroll
            for (int kd = 0; kd < 2; ++kd) {
                uint32_t bfr[2];
                bfr[0] = __float_as_uint(k_s[(kd * 8 + t) * 136 + nt * 8 + g]);
                bfr[1] = __float_as_uint(k_s[(kd * 8 + t + 4) * 136 + nt * 8 + g]);
                mma_tf32(c4, qa[kd], bfr);
            }
            s_fr[nt][0] = c4[0]; s_fr[nt][1] = c4[1];
            s_fr[nt][2] = c4[2]; s_fr[nt][3] = c4[3];
        }

        #pragma unroll
        for (int r = 0; r < 2; ++r) {
            float vm = -3.4e38f;
            #pragma unroll
            for (int nt = 0; nt < 16; ++nt)
                vm = fmaxf(vm, fmaxf(s_fr[nt][r * 2], s_fr[nt][r * 2 + 1]));
            vm = fmaxf(vm, __shfl_xor_sync(0xffffffffu, vm, 1));
            vm = fmaxf(vm, __shfl_xor_sync(0xffffffffu, vm, 2));
            float mn = fmaxf(m[r], vm);
            float corr = __expf(m[r] - mn);
            m[r] = mn;
            float ls = 0.f;
            #pragma unroll
            for (int nt = 0; nt < 16; ++nt) {
                float e0 = __expf(s_fr[nt][r * 2] - mn);
                float e1 = __expf(s_fr[nt][r * 2 + 1] - mn);
                s_fr[nt][r * 2] = e0;
                s_fr[nt][r * 2 + 1] = e1;
                ls += e0 + e1;
            }
            ls += __shfl_xor_sync(0xffffffffu, ls, 1);
            ls += __shfl_xor_sync(0xffffffffu, ls, 2);
            l[r] = l[r] * corr + ls;
            #pragma unroll
            for (int dn = 0; dn < 2; ++dn) {
                acc_o[dn][r * 2] *= corr;
                acc_o[dn][r * 2 + 1] *= corr;
            }
        }

        #pragma unroll
        for (int nt = 0; nt < 16; ++nt) {
            uint32_t pa[4];
            pa[0] = __float_as_uint(s_fr[nt][0]);
            pa[1] = __float_as_uint(s_fr[nt][2]);
            pa[2] = __float_as_uint(s_fr[nt][1]);
            pa[3] = __float_as_uint(s_fr[nt][3]);
            #pragma unroll
            for (int dn = 0; dn < 2; ++dn) {
                uint32_t bfr[2];
                bfr[0] = __float_as_uint(v_s[(nt * 8 + t) * 24 + dn * 8 + g]);
                bfr[1] = __float_as_uint(v_s[(nt * 8 + t + 4) * 24 + dn * 8 + g]);
                mma_tf32(acc_o[dn], pa, bfr);
            }
        }
    }

    #pragma unroll
    for (int r = 0; r < 2; ++r) {
        float inv = 1.f / l[r];
        int pos = q0 + wid * 16 + g + r * 8;
        int py = pos / 48, px = pos - py * 48;
        #pragma unroll
        for (int dn = 0; dn < 2; ++dn)
            #pragma unroll
            for (int cc2 = 0; cc2 < 2; ++cc2) {
                int d = dn * 8 + 2 * t + cc2;
                pad2[((size_t)b * 16 + d) * 2600 + (py + 1) * 50 + (px + 1)] =
                    acc_o[dn][r * 2 + cc2] * inv;
            }
    }
}

// ---------------- launcher ----------------
extern "C" void kernel_launch(void* const* d_in, const int* in_sizes, int n_in,
                              void* d_out, int out_size) {
    const float* x       = (const float*)d_in[0];
    const float* xe      = (const float*)d_in[1];
    const float* temb    = (const float*)d_in[2];
    const float* gn1_w   = (const float*)d_in[3];
    const float* gn1_b   = (const float*)d_in[4];
    const float* conv1_w = (const float*)d_in[5];
    const float* conv1_b = (const float*)d_in[6];
    const float* aff_w   = (const float*)d_in[7];
    const float* aff_b   = (const float*)d_in[8];
    const float* gn2_w   = (const float*)d_in[9];
    const float* gn2_b   = (const float*)d_in[10];
    const float* conv2_w = (const float*)d_in[11];
    const float* conv2_b = (const float*)d_in[12];
    const float* q_w     = (const float*)d_in[13];
    const float* kv_w    = (const float*)d_in[14];
    const float* out_w   = (const float*)d_in[15];
    const float* out_b   = (const float*)d_in[16];

    float *padp, *pad2p, *wtp, *wtBp, *wt2p, *h, *xres, *qb, *kvb, *mean, *rstd, *gbsum;
    cudaGetSymbolAddress((void**)&padp,  g_pad);
    cudaGetSymbolAddress((void**)&pad2p, g_pad2);
    cudaGetSymbolAddress((void**)&wtp,   g_wt);
    cudaGetSymbolAddress((void**)&wtBp,  g_wtB);
    cudaGetSymbolAddress((void**)&wt2p,  g_wt2);
    cudaGetSymbolAddress((void**)&h,     g_h);
    cudaGetSymbolAddress((void**)&xres,  g_xres);
    cudaGetSymbolAddress((void**)&qb,    g_q);
    cudaGetSymbolAddress((void**)&kvb,   g_kv);
    cudaGetSymbolAddress((void**)&mean,  g_mean);
    cudaGetSymbolAddress((void**)&rstd,  g_rstd);
    cudaGetSymbolAddress((void**)&gbsum, g_gbsum);

    const int DSM_C = (WRING * WBUFSZ + 2 * IBUFSZ) * 4;   // 146432 bytes
    const int DSM_16 = 4 * STG * 4;                        // 176128 bytes
    cudaFuncSetAttribute(conv_mma<0>, cudaFuncAttributeMaxDynamicSharedMemorySize, DSM_C);
    cudaFuncSetAttribute(conv_mma<1>, cudaFuncAttributeMaxDynamicSharedMemorySize, DSM_C);
    cudaFuncSetAttribute(conv_mma16, cudaFuncAttributeMaxDynamicSharedMemorySize, DSM_16);

    // 1: prep (affine + all weight transposes; 8+1296+1296+108 = 2708 blocks)
    prep_kernel<<<2708, 256>>>(temb, aff_w, aff_b, gbsum,
                               conv1_w, conv2_w, out_w, wtp, wtBp, wt2p);
    // 2, 3
    gn_stats<<<BB * 32, 256>>>(x, mean, rstd);
    gn_apply_pad<<<TOTAL / 256, 256>>>(x, mean, rstd, gn1_w, gn1_b, padp);
    // 4: conv_mma<0> (profiled slot)
    conv_mma<0><<<dim3(18, BB), 256, DSM_C>>>(padp, wtp, conv1_b, gbsum, h);

    gn_stats<<<BB * 32, 256>>>(h, mean, rstd);
    gn_apply_pad<<<TOTAL / 256, 256>>>(h, mean, rstd, gn2_w, gn2_b, padp);
    conv_mma<1><<<dim3(18, BB), 256, DSM_C>>>(padp, wtBp, conv2_b, x, xres);

    conv1x1<16><<<dim3(18, BB), 128>>>(xres, q_w, qb);
    conv1x1<32><<<dim3(18, BB), 128>>>(xe, kv_w, kvb);
    attn_mma<<<dim3(18, BB), 256>>>(qb, kvb, pad2p);
    conv_mma16<<<dim3(18, BB), 256, DSM_16>>>(pad2p, wt2p, out_b, xres, (float*)d_out);
}

// round 13
// speedup vs baseline: 1.0048x; 1.0048x over previous
#include <cuda_runtime.h>
#include <cstdint>
#include <math.h>

#define HH 48
#define WW 48
#define SP 2304
#define CC 192
#define BB 8
#define TOTAL 3538944

typedef unsigned long long u64;

// ---------------- scratch ----------------
__device__ float g_pad[BB*CC*2500];    // zero-bordered [b][c][50][50]
__device__ float g_pad2[BB*16*2600];   // zero-bordered [b][c][52][50] (attn out)
__device__ float g_wt[CC*1728];        // conv1 weights tap-major
__device__ float g_wtB[CC*1728];       // conv2 weights tap-major
__device__ float g_wt2[CC*160];        // out conv weights tap-major, K padded to 160
__device__ float g_h[TOTAL];
__device__ float g_xres[TOTAL];
__device__ float g_q[BB*16*SP];
__device__ float g_kv[BB*32*SP];
__device__ float g_mean[BB*32];
__device__ float g_rstd[BB*32];
__device__ float g_gbsum[BB*CC];

// ---------------- helpers ----------------
__device__ __forceinline__ float warp_red(float v) {
    #pragma unroll
    for (int o = 16; o > 0; o >>= 1) v += __shfl_down_sync(0xffffffffu, v, o);
    return v;
}
__device__ __forceinline__ uint32_t to_tf32(float f) {
    uint32_t r; asm("cvt.rna.tf32.f32 %0, %1;" : "=r"(r) : "f"(f)); return r;
}
__device__ __forceinline__ void mma_tf32(float c[4], const uint32_t a[4], const uint32_t b[2]) {
    asm volatile(
        "mma.sync.aligned.m16n8k8.row.col.f32.tf32.tf32.f32 "
        "{%0,%1,%2,%3}, {%4,%5,%6,%7}, {%8,%9}, {%0,%1,%2,%3};"
        : "+f"(c[0]), "+f"(c[1]), "+f"(c[2]), "+f"(c[3])
        : "r"(a[0]), "r"(a[1]), "r"(a[2]), "r"(a[3]), "r"(b[0]), "r"(b[1]));
}
__device__ __forceinline__ void ldsm_x4(uint32_t r[4], uint32_t addr) {
    asm volatile("ldmatrix.sync.aligned.m8n8.x4.shared.b16 {%0,%1,%2,%3}, [%4];"
        : "=r"(r[0]), "=r"(r[1]), "=r"(r[2]), "=r"(r[3]) : "r"(addr));
}
__device__ __forceinline__ uint32_t smaddr(const void* p) {
    return (uint32_t)__cvta_generic_to_shared(p);
}
__device__ __forceinline__ void cp4(uint32_t dst, const void* src) {
    asm volatile("cp.async.ca.shared.global [%0], [%1], 4;" :: "r"(dst), "l"(src));
}
__device__ __forceinline__ void cp16(uint32_t dst, const void* src) {
    asm volatile("cp.async.cg.shared.global [%0], [%1], 16;" :: "r"(dst), "l"(src));
}
#define CP_COMMIT() asm volatile("cp.async.commit_group;" ::: "memory")
#define CP_WAIT2()  asm volatile("cp.async.wait_group 2;" ::: "memory")

// ---------------- prep: affine + all 3 weight transposes in one launch ----------------
__global__ __launch_bounds__(256) void prep_kernel(const float* __restrict__ temb,
                                                   const float* __restrict__ aw,
                                                   const float* __restrict__ ab,
                                                   float* __restrict__ gbsum,
                                                   const float* __restrict__ w1,
                                                   const float* __restrict__ w2,
                                                   const float* __restrict__ w3,
                                                   float* __restrict__ o1,
                                                   float* __restrict__ o2,
                                                   float* __restrict__ o3) {
    int bx = blockIdx.x;
    int tid = threadIdx.x;
    if (bx < 8) {
        if (tid < 192) {
            __shared__ float t[192];
            t[tid] = temb[bx * 192 + tid];
            __syncthreads();
            float s = ab[tid] + ab[192 + tid];
            const float* wa = aw + tid * 192;
            const float* wb = aw + (192 + tid) * 192;
            for (int e = 0; e < 192; ++e) s = fmaf(t[e], wa[e] + wb[e], s);
            gbsum[bx * 192 + tid] = 0.5f * s;
        } else {
            __syncthreads();
        }
    } else if (bx < 8 + 1296) {
        int i = (bx - 8) * 256 + tid;
        if (i < CC * 1728) {
            int n = i / 1728;
            int k = i - n * 1728;
            int ci = k / 9;
            int tap = k - ci * 9;
            o1[n * 1728 + tap * 192 + ci] = w1[i];
        }
    } else if (bx < 8 + 2592) {
        int i = (bx - 8 - 1296) * 256 + tid;
        if (i < CC * 1728) {
            int n = i / 1728;
            int k = i - n * 1728;
            int ci = k / 9;
            int tap = k - ci * 9;
            o2[n * 1728 + tap * 192 + ci] = w2[i];
        }
    } else {
        int i = (bx - 8 - 2592) * 256 + tid;   // 108 blocks: full 192*144 coverage
        if (i < CC * 144) {
            int n = i / 144;
            int k = i - n * 144;
            int ci = k / 9;
            int tap = k - ci * 9;
            o3[n * 160 + tap * 16 + ci] = w3[i];
        }
    }
}

// ---------------- GroupNorm stats ----------------
__global__ __launch_bounds__(256) void gn_stats(const float* __restrict__ in,
                                                float* __restrict__ mean,
                                                float* __restrict__ rstd) {
    int bg = blockIdx.x;
    const float* base = in + (long)bg * 13824;
    float s = 0.f, s2 = 0.f;
    for (int i = threadIdx.x; i < 13824; i += 256) {
        float v = base[i];
        s += v; s2 = fmaf(v, v, s2);
    }
    __shared__ float shs[8], shs2[8];
    int w = threadIdx.x >> 5, l = threadIdx.x & 31;
    s = warp_red(s); s2 = warp_red(s2);
    if (l == 0) { shs[w] = s; shs2[w] = s2; }
    __syncthreads();
    if (w == 0) {
        s  = (l < 8) ? shs[l]  : 0.f;
        s2 = (l < 8) ? shs2[l] : 0.f;
        s = warp_red(s); s2 = warp_red(s2);
        if (l == 0) {
            float m = s * (1.f / 13824.f);
            float var = s2 * (1.f / 13824.f) - m * m;
            mean[bg] = m;
            rstd[bg] = rsqrtf(var + 1e-5f);
        }
    }
}

// ---------------- GroupNorm apply + swish -> padded [b][c][50][50] ----------------
__global__ __launch_bounds__(256) void gn_apply_pad(const float* __restrict__ in,
                                                    const float* __restrict__ mean,
                                                    const float* __restrict__ rstd,
                                                    const float* __restrict__ w,
                                                    const float* __restrict__ bb,
                                                    float* __restrict__ outpad) {
    int idx = blockIdx.x * 256 + threadIdx.x;
    int bc = idx / SP;
    int sp = idx - bc * SP;
    int b = bc / CC;
    int c = bc - b * CC;
    int sidx = b * 32 + c / 6;
    float y = (in[idx] - mean[sidx]) * rstd[sidx] * w[c] + bb[c];
    y = y / (1.f + __expf(-y));
    int py = sp / 48, px = sp - py * 48;
    outpad[(size_t)bc * 2500 + (py + 1) * 50 + (px + 1)] = y;
}

// ---------------- direct-shift TF32 mma conv (CIN=192, OC=192) --------------------
// R10 bodies EXACT, reparameterized for 2 CTAs/SM: CTA = 128 threads, 96 output
// channels (chalf) x 128 positions. grid (18, 2, 8) = 288 CTAs = 2 per SM, so one
// CTA computes while the other waits at its barrier.
#define WROW 20
#define WBUFSZ2 (96 * WROW)        // 1920 floats per weight stage
#define IBUFSZ (16 * 184)          // 2944 floats per input buffer
#define IOFF2 (4 * WBUFSZ2)
template<int EPI>
__global__ __launch_bounds__(128) void conv_mma(const float* __restrict__ pad,
                                                const float* __restrict__ wt,
                                                const float* __restrict__ bias,
                                                const float* __restrict__ extra,
                                                float* __restrict__ out) {
    extern __shared__ float sm[];

    const int mtile = blockIdx.x;       // 0..17
    const int chalf = blockIdx.y;       // 0..1 (output channel half)
    const int b = blockIdx.z;
    const int tr = mtile / 3;           // row-tile 0..5 (8 rows)
    const int tcl = mtile - tr * 3;     // col-tile 0..2 (16 cols)
    const int tid = threadIdx.x;
    const int wid = tid >> 5;           // 0..3
    const int lane = tid & 31;
    const int g = lane >> 2;
    const int t = lane & 3;
    const int wm = wid & 1;             // 2 M tiles of 48 channels
    const int wn = wid >> 1;            // 2 N tiles of 64 positions

    const float* padb = pad + (size_t)b * CC * 2500;

    const uint32_t lane_a_off =
        ((uint32_t)((wm * 48 + (lane & 15)) * WROW + ((lane >> 4) << 2))) << 2;

    auto stage = [&](int s) {
        int c = s / 9;
        int tap = s - c * 9;
        float* wbuf = sm + (s & 3) * WBUFSZ2;
        #pragma unroll
        for (int it = 0; it < 3; ++it) {
            int idx = it * 128 + tid;
            int n = idx >> 2;           // 0..95
            int kq = (idx & 3) * 4;
            cp16(smaddr(&wbuf[n * WROW + kq]),
                 wt + (size_t)(chalf * 96 + n) * 1728 + tap * 192 + c * 16 + kq);
        }
        if (tap == 0) {
            float* ibuf = sm + IOFF2 + (c & 1) * IBUFSZ;
            #pragma unroll
            for (int it = 0; it < 23; ++it) {
                int idx = it * 128 + tid;
                if (idx < 2880) {
                    int ci = idx / 180;
                    int rem = idx - ci * 180;
                    int rr = rem / 18;
                    int cc2 = rem - rr * 18;
                    cp4(smaddr(&ibuf[ci * 184 + rr * 18 + cc2]),
                        padb + (size_t)(c * 16 + ci) * 2500
                             + (tr * 8 + rr) * 50 + tcl * 16 + cc2);
                }
            }
        }
    };

    stage(0); CP_COMMIT();
    stage(1); CP_COMMIT();
    stage(2); CP_COMMIT();

    float acc[3][8][4];
    #pragma unroll
    for (int i = 0; i < 3; ++i)
        #pragma unroll
        for (int j = 0; j < 8; ++j)
            #pragma unroll
            for (int q = 0; q < 4; ++q) acc[i][j][q] = 0.f;

    for (int s = 0; s < 108; ++s) {
        CP_WAIT2();
        __syncthreads();
        const int c = s / 9;
        const int tap = s - c * 9;
        const int dy = tap / 3;
        const int dx = tap - dy * 3;
        const uint32_t wb_addr = smaddr(sm + (s & 3) * WBUFSZ2) + lane_a_off;
        const float* ib = sm + IOFF2 + (c & 1) * IBUFSZ
                        + dy * 18 + dx + t * 184 + wn * 72 + g;
        #pragma unroll
        for (int ks = 0; ks < 2; ++ks) {
            const float* ibk = ib + ks * (8 * 184);
            uint32_t afr[3][4];
            #pragma unroll
            for (int i = 0; i < 3; ++i)
                ldsm_x4(afr[i], wb_addr + i * (16 * WROW * 4) + ks * 32);
            uint32_t bfr[8][2];
            #pragma unroll
            for (int j = 0; j < 8; ++j) {
                const float* a = ibk + (j >> 1) * 18 + (j & 1) * 8;
                bfr[j][0] = *(const uint32_t*)a;
                bfr[j][1] = *(const uint32_t*)(a + 4 * 184);
            }
            #pragma unroll
            for (int i = 0; i < 3; ++i)
                #pragma unroll
                for (int j = 0; j < 8; ++j)
                    mma_tf32(acc[i][j], afr[i], bfr[j]);
        }
        if (s + 3 < 108) stage(s + 3);
        CP_COMMIT();
    }

    // epilogue: tile position n -> (y,x); coalesced float2 stores
    #pragma unroll
    for (int i = 0; i < 3; ++i) {
        const int ch0 = chalf * 96 + wm * 48 + i * 16 + g;
        const int ch1 = ch0 + 8;
        const float bv0 = bias[ch0], bv1 = bias[ch1];
        float ga0 = 0.f, ga1 = 0.f;
        if (EPI == 0) { ga0 = extra[b * CC + ch0]; ga1 = extra[b * CC + ch1]; }
        #pragma unroll
        for (int j = 0; j < 8; ++j) {
            const int n = wn * 64 + j * 8 + 2 * t;
            const int yy = tr * 8 + (n >> 4);
            const int xx = tcl * 16 + (n & 15);
            long idx0 = (((long)b * CC + ch0) * 48 + yy) * 48 + xx;
            long idx1 = (((long)b * CC + ch1) * 48 + yy) * 48 + xx;
            float y0 = acc[i][j][0] + bv0;
            float y1 = acc[i][j][1] + bv0;
            float y2 = acc[i][j][2] + bv1;
            float y3 = acc[i][j][3] + bv1;
            if (EPI == 0) {
                y0 += ga0 * y0 + ga0; y1 += ga0 * y1 + ga0;
                y2 += ga1 * y2 + ga1; y3 += ga1 * y3 + ga1;
            } else {
                float2 e0 = *(const float2*)(extra + idx0);
                float2 e1 = *(const float2*)(extra + idx1);
                y0 += e0.x; y1 += e0.y; y2 += e1.x; y3 += e1.y;
            }
            *(float2*)(out + idx0) = make_float2(y0, y1);
            *(float2*)(out + idx1) = make_float2(y2, y3);
        }
    }
}

// ---------------- out conv: CIN=16 (K padded to 160), im2col pipeline ----------------
#define WST 36
#define ASZ (192 * WST)
#define BSZ (32 * 128)
#define STG (ASZ + BSZ)
__global__ __launch_bounds__(256) void conv_mma16(const float* __restrict__ pad2,
                                                  const float* __restrict__ wt,
                                                  const float* __restrict__ bias,
                                                  const float* __restrict__ extra,
                                                  float* __restrict__ out) {
    extern __shared__ float smf[];
    uint32_t* sm = (uint32_t*)smf;

    const int mtile = blockIdx.x;
    const int b = blockIdx.y;
    const int tid = threadIdx.x;
    const int wid = tid >> 5;
    const int lane = tid & 31;
    const int g = lane >> 2;
    const int t = lane & 3;
    const int wm = wid & 3;
    const int wn = wid >> 2;

    const int p = tid & 127;
    const int khalf = tid >> 7;
    const int pg = mtile * 128 + p;
    const int py = pg / 48;
    const int px = pg - py * 48;
    const float* padb = pad2 + (size_t)b * 16 * 2600;

    auto stage = [&](int c) {
        uint32_t* buf = sm + (c & 3) * STG;
        const int tap = 2 * c + khalf;
        const int dy = tap / 3;
        const int dx = tap - dy * 3;
        const float* bsrc = padb + (py + dy) * 50 + (px + dx);
        uint32_t* Bs = buf + ASZ;
        #pragma unroll
        for (int i = 0; i < 16; ++i) {
            int kk = khalf * 16 + i;
            cp4(smaddr(&Bs[kk * 128 + (p ^ ((kk & 3) * 8))]), bsrc + (size_t)i * 2600);
        }
        #pragma unroll
        for (int it = 0; it < 6; ++it) {
            int idx = it * 256 + tid;
            int n = idx >> 3;
            int kq = (idx & 7) * 4;
            cp16(smaddr(&buf[n * WST + kq]), wt + (size_t)n * 160 + c * 32 + kq);
        }
    };

    stage(0); CP_COMMIT();
    stage(1); CP_COMMIT();
    stage(2); CP_COMMIT();

    float acc[3][8][4];
    #pragma unroll
    for (int i = 0; i < 3; ++i)
        #pragma unroll
        for (int j = 0; j < 8; ++j)
            #pragma unroll
            for (int q = 0; q < 4; ++q) acc[i][j][q] = 0.f;

    for (int c = 0; c < 5; ++c) {
        CP_WAIT2();
        __syncthreads();
        const uint32_t* Wp = sm + (c & 3) * STG;
        const uint32_t* Ip = Wp + ASZ;
        #pragma unroll
        for (int ks = 0; ks < 4; ++ks) {
            const int kk0 = ks * 8;
            uint32_t afr[3][4];
            #pragma unroll
            for (int i = 0; i < 3; ++i) {
                int row = wm * 48 + i * 16 + g;
                afr[i][0] = Wp[row * WST + kk0 + t];
                afr[i][1] = Wp[(row + 8) * WST + kk0 + t];
                afr[i][2] = Wp[row * WST + kk0 + t + 4];
                afr[i][3] = Wp[(row + 8) * WST + kk0 + t + 4];
            }
            uint32_t bfr[8][2];
            #pragma unroll
            for (int j = 0; j < 8; ++j) {
                int pp = wn * 64 + j * 8 + g;
                int ppx = pp ^ (t * 8);
                bfr[j][0] = Ip[(kk0 + t) * 128 + ppx];
                bfr[j][1] = Ip[(kk0 + t + 4) * 128 + ppx];
            }
            #pragma unroll
            for (int i = 0; i < 3; ++i)
                #pragma unroll
                for (int j = 0; j < 8; ++j)
                    mma_tf32(acc[i][j], afr[i], bfr[j]);
        }
        if (c + 3 < 5) stage(c + 3);
        CP_COMMIT();
    }

    #pragma unroll
    for (int i = 0; i < 3; ++i) {
        const int ch0 = wm * 48 + i * 16 + g;
        const int ch1 = ch0 + 8;
        const float bv0 = bias[ch0], bv1 = bias[ch1];
        #pragma unroll
        for (int j = 0; j < 8; ++j) {
            const int pos = mtile * 128 + wn * 64 + j * 8 + 2 * t;
            long idx0 = ((long)b * CC + ch0) * SP + pos;
            long idx1 = ((long)b * CC + ch1) * SP + pos;
            float2 e0 = *(const float2*)(extra + idx0);
            float2 e1 = *(const float2*)(extra + idx1);
            *(float2*)(out + idx0) = make_float2(acc[i][j][0] + bv0 + e0.x,
                                                 acc[i][j][1] + bv0 + e0.y);
            *(float2*)(out + idx1) = make_float2(acc[i][j][2] + bv1 + e1.x,
                                                 acc[i][j][3] + bv1 + e1.y);
        }
    }
}

// ---------------- 1x1 conv: 128 threads / 128 positions, grid (18, B) ----------------
template<int CO>
__global__ __launch_bounds__(128) void conv1x1(const float* __restrict__ in,
                                               const float* __restrict__ wgt,
                                               float* __restrict__ out) {
    const int b = blockIdx.y;
    const int p0 = blockIdx.x * 128;
    const int tid = threadIdx.x;
    __shared__ float s_w[CO * 192];
    __shared__ float s_x[16 * 128];
    for (int i = tid; i < CO * 192; i += 128) s_w[i] = wgt[i];
    float acc[CO];
    #pragma unroll
    for (int co = 0; co < CO; ++co) acc[co] = 0.f;

    for (int c0 = 0; c0 < 192; c0 += 16) {
        __syncthreads();
        for (int i = tid; i < 16 * 128; i += 128) {
            int ci = i >> 7;
            int pp = i & 127;
            s_x[i] = in[((long)b * 192 + c0 + ci) * SP + p0 + pp];
        }
        __syncthreads();
        #pragma unroll
        for (int ci = 0; ci < 16; ++ci) {
            float xv = s_x[ci * 128 + tid];
            #pragma unroll
            for (int co = 0; co < CO; ++co)
                acc[co] = fmaf(s_w[co * 192 + c0 + ci], xv, acc[co]);
        }
    }
    #pragma unroll
    for (int co = 0; co < CO; ++co)
        out[((long)b * CO + co) * SP + p0 + tid] = acc[co];
}

// ---------------- MMA flash attention -> padded [b][16][52][50] ----------------
__global__ __launch_bounds__(256) void attn_mma(const float* __restrict__ q,
                                                const float* __restrict__ kv,
                                                float* __restrict__ pad2) {
    const int b = blockIdx.y;
    const int mtile = blockIdx.x;
    const int q0 = mtile * 128;
    const int tid = threadIdx.x;
    const int wid = tid >> 5;
    const int lane = tid & 31;
    const int g = lane >> 2;
    const int t = lane & 3;

    __shared__ float k_s[16 * 136];
    __shared__ float v_s[128 * 24];

    uint32_t qa[2][4];
    #pragma unroll
    for (int kd = 0; kd < 2; ++kd)
        #pragma unroll
        for (int j = 0; j < 4; ++j) {
            int row = wid * 16 + g + (j & 1) * 8;
            int d = kd * 8 + t + (j >> 1) * 4;
            float v = q[((long)b * 16 + d) * SP + q0 + row] * 0.25f;
            qa[kd][j] = to_tf32(v);
        }

    float m[2] = { -3.4e38f, -3.4e38f };
    float l[2] = { 0.f, 0.f };
    float acc_o[2][4];
    #pragma unroll
    for (int dn = 0; dn < 2; ++dn)
        #pragma unroll
        for (int j = 0; j < 4; ++j) acc_o[dn][j] = 0.f;

    const long kvb = (long)b * 32 * SP;
    for (int kb = 0; kb < 18; ++kb) {
        __syncthreads();
        const int key0 = kb * 128;
        #pragma unroll
        for (int it = 0; it < 8; ++it) {
            int idx = it * 256 + tid;
            int c = idx >> 7;
            int key = idx & 127;
            k_s[c * 136 + key] =
                __uint_as_float(to_tf32(kv[kvb + (long)c * SP + key0 + key]));
        }
        #pragma unroll
        for (int it = 0; it < 8; ++it) {
            int idx = it * 256 + tid;
            int d = idx >> 7;
            int key = idx & 127;
            int kp = key & 7;
            int kap = (kp & 1) ? (kp >> 1) + 4 : (kp >> 1);
            int slot = (key & ~7) | kap;
            v_s[slot * 24 + d] =
                __uint_as_float(to_tf32(kv[kvb + (long)(16 + d) * SP + key0 + key]));
        }
        __syncthreads();

        float s_fr[16][4];
        #pragma unroll
        for (int nt = 0; nt < 16; ++nt) {
            float c4[4] = { 0.f, 0.f, 0.f, 0.f };
            #pragma unroll
            for (int kd = 0; kd < 2; ++kd) {
                uint32_t bfr[2];
                bfr[0] = __float_as_uint(k_s[(kd * 8 + t) * 136 + nt * 8 + g]);
                bfr[1] = __float_as_uint(k_s[(kd * 8 + t + 4) * 136 + nt * 8 + g]);
                mma_tf32(c4, qa[kd], bfr);
            }
            s_fr[nt][0] = c4[0]; s_fr[nt][1] = c4[1];
            s_fr[nt][2] = c4[2]; s_fr[nt][3] = c4[3];
        }

        #pragma unroll
        for (int r = 0; r < 2; ++r) {
            float vm = -3.4e38f;
            #pragma unroll
            for (int nt = 0; nt < 16; ++nt)
                vm = fmaxf(vm, fmaxf(s_fr[nt][r * 2], s_fr[nt][r * 2 + 1]));
            vm = fmaxf(vm, __shfl_xor_sync(0xffffffffu, vm, 1));
            vm = fmaxf(vm, __shfl_xor_sync(0xffffffffu, vm, 2));
            float mn = fmaxf(m[r], vm);
            float corr = __expf(m[r] - mn);
            m[r] = mn;
            float ls = 0.f;
            #pragma unroll
            for (int nt = 0; nt < 16; ++nt) {
                float e0 = __expf(s_fr[nt][r * 2] - mn);
                float e1 = __expf(s_fr[nt][r * 2 + 1] - mn);
                s_fr[nt][r * 2] = e0;
                s_fr[nt][r * 2 + 1] = e1;
                ls += e0 + e1;
            }
            ls += __shfl_xor_sync(0xffffffffu, ls, 1);
            ls += __shfl_xor_sync(0xffffffffu, ls, 2);
            l[r] = l[r] * corr + ls;
            #pragma unroll
            for (int dn = 0; dn < 2; ++dn) {
                acc_o[dn][r * 2] *= corr;
                acc_o[dn][r * 2 + 1] *= corr;
            }
        }

        #pragma unroll
        for (int nt = 0; nt < 16; ++nt) {
            uint32_t pa[4];
            pa[0] = __float_as_uint(s_fr[nt][0]);
            pa[1] = __float_as_uint(s_fr[nt][2]);
            pa[2] = __float_as_uint(s_fr[nt][1]);
            pa[3] = __float_as_uint(s_fr[nt][3]);
            #pragma unroll
            for (int dn = 0; dn < 2; ++dn) {
                uint32_t bfr[2];
                bfr[0] = __float_as_uint(v_s[(nt * 8 + t) * 24 + dn * 8 + g]);
                bfr[1] = __float_as_uint(v_s[(nt * 8 + t + 4) * 24 + dn * 8 + g]);
                mma_tf32(acc_o[dn], pa, bfr);
            }
        }
    }

    #pragma unroll
    for (int r = 0; r < 2; ++r) {
        float inv = 1.f / l[r];
        int pos = q0 + wid * 16 + g + r * 8;
        int py = pos / 48, px = pos - py * 48;
        #pragma unroll
        for (int dn = 0; dn < 2; ++dn)
            #pragma unroll
            for (int cc2 = 0; cc2 < 2; ++cc2) {
                int d = dn * 8 + 2 * t + cc2;
                pad2[((size_t)b * 16 + d) * 2600 + (py + 1) * 50 + (px + 1)] =
                    acc_o[dn][r * 2 + cc2] * inv;
            }
    }
}

// ---------------- launcher ----------------
extern "C" void kernel_launch(void* const* d_in, const int* in_sizes, int n_in,
                              void* d_out, int out_size) {
    const float* x       = (const float*)d_in[0];
    const float* xe      = (const float*)d_in[1];
    const float* temb    = (const float*)d_in[2];
    const float* gn1_w   = (const float*)d_in[3];
    const float* gn1_b   = (const float*)d_in[4];
    const float* conv1_w = (const float*)d_in[5];
    const float* conv1_b = (const float*)d_in[6];
    const float* aff_w   = (const float*)d_in[7];
    const float* aff_b   = (const float*)d_in[8];
    const float* gn2_w   = (const float*)d_in[9];
    const float* gn2_b   = (const float*)d_in[10];
    const float* conv2_w = (const float*)d_in[11];
    const float* conv2_b = (const float*)d_in[12];
    const float* q_w     = (const float*)d_in[13];
    const float* kv_w    = (const float*)d_in[14];
    const float* out_w   = (const float*)d_in[15];
    const float* out_b   = (const float*)d_in[16];

    float *padp, *pad2p, *wtp, *wtBp, *wt2p, *h, *xres, *qb, *kvb, *mean, *rstd, *gbsum;
    cudaGetSymbolAddress((void**)&padp,  g_pad);
    cudaGetSymbolAddress((void**)&pad2p, g_pad2);
    cudaGetSymbolAddress((void**)&wtp,   g_wt);
    cudaGetSymbolAddress((void**)&wtBp,  g_wtB);
    cudaGetSymbolAddress((void**)&wt2p,  g_wt2);
    cudaGetSymbolAddress((void**)&h,     g_h);
    cudaGetSymbolAddress((void**)&xres,  g_xres);
    cudaGetSymbolAddress((void**)&qb,    g_q);
    cudaGetSymbolAddress((void**)&kvb,   g_kv);
    cudaGetSymbolAddress((void**)&mean,  g_mean);
    cudaGetSymbolAddress((void**)&rstd,  g_rstd);
    cudaGetSymbolAddress((void**)&gbsum, g_gbsum);

    const int DSM_C = (4 * WBUFSZ2 + 2 * IBUFSZ) * 4;  // 54272 bytes (2 CTAs/SM)
    const int DSM_16 = 4 * STG * 4;                    // 176128 bytes
    cudaFuncSetAttribute(conv_mma<0>, cudaFuncAttributeMaxDynamicSharedMemorySize, DSM_C);
    cudaFuncSetAttribute(conv_mma<1>, cudaFuncAttributeMaxDynamicSharedMemorySize, DSM_C);
    cudaFuncSetAttribute(conv_mma16, cudaFuncAttributeMaxDynamicSharedMemorySize, DSM_16);

    // 1: prep (affine + all weight transposes; 8+1296+1296+108 = 2708 blocks)
    prep_kernel<<<2708, 256>>>(temb, aff_w, aff_b, gbsum,
                               conv1_w, conv2_w, out_w, wtp, wtBp, wt2p);
    // 2, 3
    gn_stats<<<BB * 32, 256>>>(x, mean, rstd);
    gn_apply_pad<<<TOTAL / 256, 256>>>(x, mean, rstd, gn1_w, gn1_b, padp);
    // 4: conv_mma<0> (profiled slot) — 2 CTAs/SM
    conv_mma<0><<<dim3(18, 2, BB), 128, DSM_C>>>(padp, wtp, conv1_b, gbsum, h);

    gn_stats<<<BB * 32, 256>>>(h, mean, rstd);
    gn_apply_pad<<<TOTAL / 256, 256>>>(h, mean, rstd, gn2_w, gn2_b, padp);
    conv_mma<1><<<dim3(18, 2, BB), 128, DSM_C>>>(padp, wtBp, conv2_b, x, xres);

    conv1x1<16><<<dim3(18, BB), 128>>>(xres, q_w, qb);
    conv1x1<32><<<dim3(18, BB), 128>>>(xe, kv_w, kvb);
    attn_mma<<<dim3(18, BB), 256>>>(qb, kvb, pad2p);
    conv_mma16<<<dim3(18, BB), 256, DSM_16>>>(pad2p, wt2p, out_b, xres, (float*)d_out);
}

// round 14
// speedup vs baseline: 1.0940x; 1.0888x over previous
#include <cuda_runtime.h>
#include <cstdint>
#include <math.h>

#define HH 48
#define WW 48
#define SP 2304
#define CC 192
#define BB 8
#define TOTAL 3538944

typedef unsigned long long u64;

// ---------------- scratch ----------------
__device__ float g_pad[BB*CC*2500];    // zero-bordered [b][c][50][50]
__device__ float g_pad2[BB*16*2600];   // zero-bordered [b][c][52][50] (attn out)
__device__ float g_wt[CC*1728];        // conv1 weights tap-major
__device__ float g_wtB[CC*1728];       // conv2 weights tap-major
__device__ float g_wt2[CC*160];        // out conv weights tap-major, K padded to 160
__device__ float g_h[TOTAL];
__device__ float g_xres[TOTAL];
__device__ float g_q[BB*16*SP];
__device__ float g_kv[BB*32*SP];
__device__ float g_mean[BB*32];
__device__ float g_rstd[BB*32];
__device__ float g_gsum[BB*32];        // fused gn2 stats accumulators
__device__ float g_gsq[BB*32];
__device__ float g_gbsum[BB*CC];

// ---------------- helpers ----------------
__device__ __forceinline__ float warp_red(float v) {
    #pragma unroll
    for (int o = 16; o > 0; o >>= 1) v += __shfl_down_sync(0xffffffffu, v, o);
    return v;
}
__device__ __forceinline__ uint32_t to_tf32(float f) {
    uint32_t r; asm("cvt.rna.tf32.f32 %0, %1;" : "=r"(r) : "f"(f)); return r;
}
__device__ __forceinline__ void mma_tf32(float c[4], const uint32_t a[4], const uint32_t b[2]) {
    asm volatile(
        "mma.sync.aligned.m16n8k8.row.col.f32.tf32.tf32.f32 "
        "{%0,%1,%2,%3}, {%4,%5,%6,%7}, {%8,%9}, {%0,%1,%2,%3};"
        : "+f"(c[0]), "+f"(c[1]), "+f"(c[2]), "+f"(c[3])
        : "r"(a[0]), "r"(a[1]), "r"(a[2]), "r"(a[3]), "r"(b[0]), "r"(b[1]));
}
__device__ __forceinline__ void ldsm_x4(uint32_t r[4], uint32_t addr) {
    asm volatile("ldmatrix.sync.aligned.m8n8.x4.shared.b16 {%0,%1,%2,%3}, [%4];"
        : "=r"(r[0]), "=r"(r[1]), "=r"(r[2]), "=r"(r[3]) : "r"(addr));
}
__device__ __forceinline__ uint32_t smaddr(const void* p) {
    return (uint32_t)__cvta_generic_to_shared(p);
}
__device__ __forceinline__ void cp4(uint32_t dst, const void* src) {
    asm volatile("cp.async.ca.shared.global [%0], [%1], 4;" :: "r"(dst), "l"(src));
}
__device__ __forceinline__ void cp16(uint32_t dst, const void* src) {
    asm volatile("cp.async.cg.shared.global [%0], [%1], 16;" :: "r"(dst), "l"(src));
}
#define CP_COMMIT() asm volatile("cp.async.commit_group;" ::: "memory")
#define CP_WAIT2()  asm volatile("cp.async.wait_group 2;" ::: "memory")

// ---------------- prep: affine + weight transposes + gn_stats(x) + zero accum --------
__global__ __launch_bounds__(256) void prep_kernel(const float* __restrict__ temb,
                                                   const float* __restrict__ aw,
                                                   const float* __restrict__ ab,
                                                   float* __restrict__ gbsum,
                                                   const float* __restrict__ w1,
                                                   const float* __restrict__ w2,
                                                   const float* __restrict__ w3,
                                                   float* __restrict__ o1,
                                                   float* __restrict__ o2,
                                                   float* __restrict__ o3,
                                                   const float* __restrict__ x,
                                                   float* __restrict__ mean,
                                                   float* __restrict__ rstd,
                                                   float* __restrict__ gsum,
                                                   float* __restrict__ gsq) {
    int bx = blockIdx.x;
    int tid = threadIdx.x;
    if (bx < 8) {
        if (tid < 192) {
            __shared__ float t[192];
            t[tid] = temb[bx * 192 + tid];
            __syncthreads();
            float s = ab[tid] + ab[192 + tid];
            const float* wa = aw + tid * 192;
            const float* wb = aw + (192 + tid) * 192;
            for (int e = 0; e < 192; ++e) s = fmaf(t[e], wa[e] + wb[e], s);
            gbsum[bx * 192 + tid] = 0.5f * s;
        } else {
            __syncthreads();
        }
    } else if (bx < 8 + 1296) {
        int i = (bx - 8) * 256 + tid;
        if (i < CC * 1728) {
            int n = i / 1728;
            int k = i - n * 1728;
            int ci = k / 9;
            int tap = k - ci * 9;
            o1[n * 1728 + tap * 192 + ci] = w1[i];
        }
    } else if (bx < 8 + 2592) {
        int i = (bx - 8 - 1296) * 256 + tid;
        if (i < CC * 1728) {
            int n = i / 1728;
            int k = i - n * 1728;
            int ci = k / 9;
            int tap = k - ci * 9;
            o2[n * 1728 + tap * 192 + ci] = w2[i];
        }
    } else if (bx < 8 + 2592 + 108) {
        int i = (bx - 8 - 2592) * 256 + tid;
        if (i < CC * 144) {
            int n = i / 144;
            int k = i - n * 144;
            int ci = k / 9;
            int tap = k - ci * 9;
            o3[n * 160 + tap * 16 + ci] = w3[i];
        }
    } else if (bx < 8 + 2592 + 108 + 256) {
        // gn_stats for x, group bg
        int bg = bx - 2708;
        const float* base = x + (long)bg * 13824;
        float s = 0.f, s2 = 0.f;
        for (int i = tid; i < 13824; i += 256) {
            float v = base[i];
            s += v; s2 = fmaf(v, v, s2);
        }
        __shared__ float shs[8], shs2[8];
        int w = tid >> 5, l = tid & 31;
        s = warp_red(s); s2 = warp_red(s2);
        if (l == 0) { shs[w] = s; shs2[w] = s2; }
        __syncthreads();
        if (w == 0) {
            s  = (l < 8) ? shs[l]  : 0.f;
            s2 = (l < 8) ? shs2[l] : 0.f;
            s = warp_red(s); s2 = warp_red(s2);
            if (l == 0) {
                float m = s * (1.f / 13824.f);
                float var = s2 * (1.f / 13824.f) - m * m;
                mean[bg] = m;
                rstd[bg] = rsqrtf(var + 1e-5f);
            }
        }
    } else {
        gsum[tid] = 0.f;
        gsq[tid] = 0.f;
    }
}

// ---------------- GroupNorm apply + swish -> padded [b][c][50][50] ----------------
__global__ __launch_bounds__(256) void gn_apply_pad(const float* __restrict__ in,
                                                    const float* __restrict__ mean,
                                                    const float* __restrict__ rstd,
                                                    const float* __restrict__ w,
                                                    const float* __restrict__ bb,
                                                    float* __restrict__ outpad) {
    int idx = blockIdx.x * 256 + threadIdx.x;
    int bc = idx / SP;
    int sp = idx - bc * SP;
    int b = bc / CC;
    int c = bc - b * CC;
    int sidx = b * 32 + c / 6;
    float y = (in[idx] - mean[sidx]) * rstd[sidx] * w[c] + bb[c];
    y = y / (1.f + __expf(-y));
    int py = sp / 48, px = sp - py * 48;
    outpad[(size_t)bc * 2500 + (py + 1) * 50 + (px + 1)] = y;
}

// same, from raw (sum, sumsq) accumulators
__global__ __launch_bounds__(256) void gn_apply_pad_fused(const float* __restrict__ in,
                                                          const float* __restrict__ gsum,
                                                          const float* __restrict__ gsq,
                                                          const float* __restrict__ w,
                                                          const float* __restrict__ bb,
                                                          float* __restrict__ outpad) {
    int idx = blockIdx.x * 256 + threadIdx.x;
    int bc = idx / SP;
    int sp = idx - bc * SP;
    int b = bc / CC;
    int c = bc - b * CC;
    int sidx = b * 32 + c / 6;
    float s = __ldg(&gsum[sidx]);
    float s2 = __ldg(&gsq[sidx]);
    float mn = s * (1.f / 13824.f);
    float rs = rsqrtf(s2 * (1.f / 13824.f) - mn * mn + 1e-5f);
    float y = (in[idx] - mn) * rs * w[c] + bb[c];
    y = y / (1.f + __expf(-y));
    int py = sp / 48, px = sp - py * 48;
    outpad[(size_t)bc * 2500 + (py + 1) * 50 + (px + 1)] = y;
}

// ---------------- direct-shift TF32 mma conv (CIN=192, OC=192) --------------------
// R10 body EXACT (HW-verified 79.4us). EPI 0 additionally accumulates gn2 stats
// in the epilogue (R8-verified, +0.3us) so gn_stats(h) launch is eliminated.
#define WROW 20
#define WBUFSZ (192 * WROW)       // 3840 floats per weight stage
#define IBUFSZ (16 * 184)         // 2944 floats per input buffer
#define IOFF (4 * WBUFSZ)
template<int EPI>
__global__ __launch_bounds__(256) void conv_mma(const float* __restrict__ pad,
                                                const float* __restrict__ wt,
                                                const float* __restrict__ bias,
                                                const float* __restrict__ extra,
                                                float* __restrict__ out,
                                                float* __restrict__ gsum,
                                                float* __restrict__ gsq) {
    extern __shared__ float sm[];

    const int mtile = blockIdx.x;       // 0..17
    const int b = blockIdx.y;
    const int tr = mtile / 3;           // row-tile 0..5 (8 rows)
    const int tcl = mtile - tr * 3;     // col-tile 0..2 (16 cols)
    const int tid = threadIdx.x;
    const int wid = tid >> 5;
    const int lane = tid & 31;
    const int g = lane >> 2;
    const int t = lane & 3;
    const int wm = wid & 3;             // 4 M tiles of 48 channels
    const int wn = wid >> 2;            // 2 N tiles of 64 positions

    const float* padb = pad + (size_t)b * CC * 2500;

    const uint32_t lane_a_off =
        ((uint32_t)((wm * 48 + (lane & 15)) * WROW + ((lane >> 4) << 2))) << 2;

    auto stage = [&](int s) {
        int c = s / 9;
        int tap = s - c * 9;
        float* wbuf = sm + (s & 3) * WBUFSZ;
        #pragma unroll
        for (int it = 0; it < 3; ++it) {
            int idx = it * 256 + tid;
            int n = idx >> 2;
            int kq = (idx & 3) * 4;
            cp16(smaddr(&wbuf[n * WROW + kq]),
                 wt + (size_t)n * 1728 + tap * 192 + c * 16 + kq);
        }
        if (tap == 0) {
            float* ibuf = sm + IOFF + (c & 1) * IBUFSZ;
            #pragma unroll
            for (int it = 0; it < 12; ++it) {
                int idx = it * 256 + tid;
                if (idx < 2880) {
                    int ci = idx / 180;
                    int rem = idx - ci * 180;
                    int rr = rem / 18;
                    int cc2 = rem - rr * 18;
                    cp4(smaddr(&ibuf[ci * 184 + rr * 18 + cc2]),
                        padb + (size_t)(c * 16 + ci) * 2500
                             + (tr * 8 + rr) * 50 + tcl * 16 + cc2);
                }
            }
        }
    };

    stage(0); CP_COMMIT();
    stage(1); CP_COMMIT();
    stage(2); CP_COMMIT();

    float acc[3][8][4];
    #pragma unroll
    for (int i = 0; i < 3; ++i)
        #pragma unroll
        for (int j = 0; j < 8; ++j)
            #pragma unroll
            for (int q = 0; q < 4; ++q) acc[i][j][q] = 0.f;

    for (int s = 0; s < 108; ++s) {
        CP_WAIT2();
        __syncthreads();
        const int c = s / 9;
        const int tap = s - c * 9;
        const int dy = tap / 3;
        const int dx = tap - dy * 3;
        const uint32_t wb_addr = smaddr(sm + (s & 3) * WBUFSZ) + lane_a_off;
        const float* ib = sm + IOFF + (c & 1) * IBUFSZ
                        + dy * 18 + dx + t * 184 + wn * 72 + g;
        #pragma unroll
        for (int ks = 0; ks < 2; ++ks) {
            const float* ibk = ib + ks * (8 * 184);
            uint32_t afr[3][4];
            #pragma unroll
            for (int i = 0; i < 3; ++i)
                ldsm_x4(afr[i], wb_addr + i * (16 * WROW * 4) + ks * 32);
            uint32_t bfr[8][2];
            #pragma unroll
            for (int j = 0; j < 8; ++j) {
                const float* a = ibk + (j >> 1) * 18 + (j & 1) * 8;
                bfr[j][0] = *(const uint32_t*)a;
                bfr[j][1] = *(const uint32_t*)(a + 4 * 184);
            }
            #pragma unroll
            for (int i = 0; i < 3; ++i)
                #pragma unroll
                for (int j = 0; j < 8; ++j)
                    mma_tf32(acc[i][j], afr[i], bfr[j]);
        }
        if (s + 3 < 108) stage(s + 3);
        CP_COMMIT();
    }

    // ---- epilogue (R10 stores; EPI==0 adds R8-verified stats accumulation) ----
    __shared__ float sgs[32], sgq[32];
    if (EPI == 0) {
        if (tid < 32) { sgs[tid] = 0.f; sgq[tid] = 0.f; }
        __syncthreads();
    }
    #pragma unroll
    for (int i = 0; i < 3; ++i) {
        const int ch0 = wm * 48 + i * 16 + g;
        const int ch1 = ch0 + 8;
        const float bv0 = bias[ch0], bv1 = bias[ch1];
        float ga0 = 0.f, ga1 = 0.f;
        if (EPI == 0) { ga0 = extra[b * CC + ch0]; ga1 = extra[b * CC + ch1]; }
        float ps0 = 0.f, pq0 = 0.f, ps1 = 0.f, pq1 = 0.f;
        #pragma unroll
        for (int j = 0; j < 8; ++j) {
            const int n = wn * 64 + j * 8 + 2 * t;
            const int yy = tr * 8 + (n >> 4);
            const int xx = tcl * 16 + (n & 15);
            long idx0 = (((long)b * CC + ch0) * 48 + yy) * 48 + xx;
            long idx1 = (((long)b * CC + ch1) * 48 + yy) * 48 + xx;
            float y0 = acc[i][j][0] + bv0;
            float y1 = acc[i][j][1] + bv0;
            float y2 = acc[i][j][2] + bv1;
            float y3 = acc[i][j][3] + bv1;
            if (EPI == 0) {
                y0 += ga0 * y0 + ga0; y1 += ga0 * y1 + ga0;
                y2 += ga1 * y2 + ga1; y3 += ga1 * y3 + ga1;
                ps0 += y0 + y1; pq0 += y0 * y0 + y1 * y1;
                ps1 += y2 + y3; pq1 += y2 * y2 + y3 * y3;
            } else {
                float2 e0 = *(const float2*)(extra + idx0);
                float2 e1 = *(const float2*)(extra + idx1);
                y0 += e0.x; y1 += e0.y; y2 += e1.x; y3 += e1.y;
            }
            *(float2*)(out + idx0) = make_float2(y0, y1);
            *(float2*)(out + idx1) = make_float2(y2, y3);
        }
        if (EPI == 0) {
            ps0 += __shfl_xor_sync(0xffffffffu, ps0, 1);
            ps0 += __shfl_xor_sync(0xffffffffu, ps0, 2);
            pq0 += __shfl_xor_sync(0xffffffffu, pq0, 1);
            pq0 += __shfl_xor_sync(0xffffffffu, pq0, 2);
            ps1 += __shfl_xor_sync(0xffffffffu, ps1, 1);
            ps1 += __shfl_xor_sync(0xffffffffu, ps1, 2);
            pq1 += __shfl_xor_sync(0xffffffffu, pq1, 1);
            pq1 += __shfl_xor_sync(0xffffffffu, pq1, 2);
            if (t == 0) {
                atomicAdd(&sgs[ch0 / 6], ps0);
                atomicAdd(&sgq[ch0 / 6], pq0);
                atomicAdd(&sgs[ch1 / 6], ps1);
                atomicAdd(&sgq[ch1 / 6], pq1);
            }
        }
    }
    if (EPI == 0) {
        __syncthreads();
        if (tid < 32) {
            atomicAdd(&gsum[b * 32 + tid], sgs[tid]);
            atomicAdd(&gsq[b * 32 + tid], sgq[tid]);
        }
    }
}

// ---------------- out conv: CIN=16 (K padded to 160), im2col pipeline ----------------
#define WST 36
#define ASZ (192 * WST)
#define BSZ (32 * 128)
#define STG (ASZ + BSZ)
__global__ __launch_bounds__(256) void conv_mma16(const float* __restrict__ pad2,
                                                  const float* __restrict__ wt,
                                                  const float* __restrict__ bias,
                                                  const float* __restrict__ extra,
                                                  float* __restrict__ out) {
    extern __shared__ float smf[];
    uint32_t* sm = (uint32_t*)smf;

    const int mtile = blockIdx.x;
    const int b = blockIdx.y;
    const int tid = threadIdx.x;
    const int wid = tid >> 5;
    const int lane = tid & 31;
    const int g = lane >> 2;
    const int t = lane & 3;
    const int wm = wid & 3;
    const int wn = wid >> 2;

    const int p = tid & 127;
    const int khalf = tid >> 7;
    const int pg = mtile * 128 + p;
    const int py = pg / 48;
    const int px = pg - py * 48;
    const float* padb = pad2 + (size_t)b * 16 * 2600;

    auto stage = [&](int c) {
        uint32_t* buf = sm + (c & 3) * STG;
        const int tap = 2 * c + khalf;
        const int dy = tap / 3;
        const int dx = tap - dy * 3;
        const float* bsrc = padb + (py + dy) * 50 + (px + dx);
        uint32_t* Bs = buf + ASZ;
        #pragma unroll
        for (int i = 0; i < 16; ++i) {
            int kk = khalf * 16 + i;
            cp4(smaddr(&Bs[kk * 128 + (p ^ ((kk & 3) * 8))]), bsrc + (size_t)i * 2600);
        }
        #pragma unroll
        for (int it = 0; it < 6; ++it) {
            int idx = it * 256 + tid;
            int n = idx >> 3;
            int kq = (idx & 7) * 4;
            cp16(smaddr(&buf[n * WST + kq]), wt + (size_t)n * 160 + c * 32 + kq);
        }
    };

    stage(0); CP_COMMIT();
    stage(1); CP_COMMIT();
    stage(2); CP_COMMIT();

    float acc[3][8][4];
    #pragma unroll
    for (int i = 0; i < 3; ++i)
        #pragma unroll
        for (int j = 0; j < 8; ++j)
            #pragma unroll
            for (int q = 0; q < 4; ++q) acc[i][j][q] = 0.f;

    for (int c = 0; c < 5; ++c) {
        CP_WAIT2();
        __syncthreads();
        const uint32_t* Wp = sm + (c & 3) * STG;
        const uint32_t* Ip = Wp + ASZ;
        #pragma unroll
        for (int ks = 0; ks < 4; ++ks) {
            const int kk0 = ks * 8;
            uint32_t afr[3][4];
            #pragma unroll
            for (int i = 0; i < 3; ++i) {
                int row = wm * 48 + i * 16 + g;
                afr[i][0] = Wp[row * WST + kk0 + t];
                afr[i][1] = Wp[(row + 8) * WST + kk0 + t];
                afr[i][2] = Wp[row * WST + kk0 + t + 4];
                afr[i][3] = Wp[(row + 8) * WST + kk0 + t + 4];
            }
            uint32_t bfr[8][2];
            #pragma unroll
            for (int j = 0; j < 8; ++j) {
                int pp = wn * 64 + j * 8 + g;
                int ppx = pp ^ (t * 8);
                bfr[j][0] = Ip[(kk0 + t) * 128 + ppx];
                bfr[j][1] = Ip[(kk0 + t + 4) * 128 + ppx];
            }
            #pragma unroll
            for (int i = 0; i < 3; ++i)
                #pragma unroll
                for (int j = 0; j < 8; ++j)
                    mma_tf32(acc[i][j], afr[i], bfr[j]);
        }
        if (c + 3 < 5) stage(c + 3);
        CP_COMMIT();
    }

    #pragma unroll
    for (int i = 0; i < 3; ++i) {
        const int ch0 = wm * 48 + i * 16 + g;
        const int ch1 = ch0 + 8;
        const float bv0 = bias[ch0], bv1 = bias[ch1];
        #pragma unroll
        for (int j = 0; j < 8; ++j) {
            const int pos = mtile * 128 + wn * 64 + j * 8 + 2 * t;
            long idx0 = ((long)b * CC + ch0) * SP + pos;
            long idx1 = ((long)b * CC + ch1) * SP + pos;
            float2 e0 = *(const float2*)(extra + idx0);
            float2 e1 = *(const float2*)(extra + idx1);
            *(float2*)(out + idx0) = make_float2(acc[i][j][0] + bv0 + e0.x,
                                                 acc[i][j][1] + bv0 + e0.y);
            *(float2*)(out + idx1) = make_float2(acc[i][j][2] + bv1 + e1.x,
                                                 acc[i][j][3] + bv1 + e1.y);
        }
    }
}

// ---------------- merged 1x1 convs: z=0 -> q (CO=16), z=1 -> kv (CO=32) --------------
template<int CO>
__device__ __forceinline__ void conv1x1_body(const float* __restrict__ in,
                                             const float* __restrict__ wgt,
                                             float* __restrict__ out,
                                             float* s_w, float* s_x,
                                             int b, int p0, int tid) {
    for (int i = tid; i < CO * 192; i += 128) s_w[i] = wgt[i];
    float acc[CO];
    #pragma unroll
    for (int co = 0; co < CO; ++co) acc[co] = 0.f;

    for (int c0 = 0; c0 < 192; c0 += 16) {
        __syncthreads();
        for (int i = tid; i < 16 * 128; i += 128) {
            int ci = i >> 7;
            int pp = i & 127;
            s_x[i] = in[((long)b * 192 + c0 + ci) * SP + p0 + pp];
        }
        __syncthreads();
        #pragma unroll
        for (int ci = 0; ci < 16; ++ci) {
            float xv = s_x[ci * 128 + tid];
            #pragma unroll
            for (int co = 0; co < CO; ++co)
                acc[co] = fmaf(s_w[co * 192 + c0 + ci], xv, acc[co]);
        }
    }
    #pragma unroll
    for (int co = 0; co < CO; ++co)
        out[((long)b * CO + co) * SP + p0 + tid] = acc[co];
}

__global__ __launch_bounds__(128) void conv1x1_both(const float* __restrict__ xres,
                                                    const float* __restrict__ q_w,
                                                    float* __restrict__ qb,
                                                    const float* __restrict__ xe,
                                                    const float* __restrict__ kv_w,
                                                    float* __restrict__ kvb) {
    extern __shared__ float smem[];
    float* s_w = smem;              // up to 32*192
    float* s_x = smem + 32 * 192;   // 16*128
    const int b = blockIdx.y;
    const int p0 = blockIdx.x * 128;
    const int tid = threadIdx.x;
    if (blockIdx.z == 0)
        conv1x1_body<16>(xres, q_w, qb, s_w, s_x, b, p0, tid);
    else
        conv1x1_body<32>(xe, kv_w, kvb, s_w, s_x, b, p0, tid);
}

// ---------------- MMA flash attention -> padded [b][16][52][50] ----------------
__global__ __launch_bounds__(256) void attn_mma(const float* __restrict__ q,
                                                const float* __restrict__ kv,
                                                float* __restrict__ pad2) {
    const int b = blockIdx.y;
    const int mtile = blockIdx.x;
    const int q0 = mtile * 128;
    const int tid = threadIdx.x;
    const int wid = tid >> 5;
    const int lane = tid & 31;
    const int g = lane >> 2;
    const int t = lane & 3;

    __shared__ float k_s[16 * 136];
    __shared__ float v_s[128 * 24];

    uint32_t qa[2][4];
    #pragma unroll
    for (int kd = 0; kd < 2; ++kd)
        #pragma unroll
        for (int j = 0; j < 4; ++j) {
            int row = wid * 16 + g + (j & 1) * 8;
            int d = kd * 8 + t + (j >> 1) * 4;
            float v = q[((long)b * 16 + d) * SP + q0 + row] * 0.25f;
            qa[kd][j] = to_tf32(v);
        }

    float m[2] = { -3.4e38f, -3.4e38f };
    float l[2] = { 0.f, 0.f };
    float acc_o[2][4];
    #pragma unroll
    for (int dn = 0; dn < 2; ++dn)
        #pragma unroll
        for (int j = 0; j < 4; ++j) acc_o[dn][j] = 0.f;

    const long kvb = (long)b * 32 * SP;
    for (int kb = 0; kb < 18; ++kb) {
        __syncthreads();
        const int key0 = kb * 128;
        #pragma unroll
        for (int it = 0; it < 8; ++it) {
            int idx = it * 256 + tid;
            int c = idx >> 7;
            int key = idx & 127;
            k_s[c * 136 + key] =
                __uint_as_float(to_tf32(kv[kvb + (long)c * SP + key0 + key]));
        }
        #pragma unroll
        for (int it = 0; it < 8; ++it) {
            int idx = it * 256 + tid;
            int d = idx >> 7;
            int key = idx & 127;
            int kp = key & 7;
            int kap = (kp & 1) ? (kp >> 1) + 4 : (kp >> 1);
            int slot = (key & ~7) | kap;
            v_s[slot * 24 + d] =
                __uint_as_float(to_tf32(kv[kvb + (long)(16 + d) * SP + key0 + key]));
        }
        __syncthreads();

        float s_fr[16][4];
        #pragma unroll
        for (int nt = 0; nt < 16; ++nt) {
            float c4[4] = { 0.f, 0.f, 0.f, 0.f };
            #pragma unroll
            for (int kd = 0; kd < 2; ++kd) {
                uint32_t bfr[2];
                bfr[0] = __float_as_uint(k_s[(kd * 8 + t) * 136 + nt * 8 + g]);
                bfr[1] = __float_as_uint(k_s[(kd * 8 + t + 4) * 136 + nt * 8 + g]);
                mma_tf32(c4, qa[kd], bfr);
            }
            s_fr[nt][0] = c4[0]; s_fr[nt][1] = c4[1];
            s_fr[nt][2] = c4[2]; s_fr[nt][3] = c4[3];
        }

        #pragma unroll
        for (int r = 0; r < 2; ++r) {
            float vm = -3.4e38f;
            #pragma unroll
            for (int nt = 0; nt < 16; ++nt)
                vm = fmaxf(vm, fmaxf(s_fr[nt][r * 2], s_fr[nt][r * 2 + 1]));
            vm = fmaxf(vm, __shfl_xor_sync(0xffffffffu, vm, 1));
            vm = fmaxf(vm, __shfl_xor_sync(0xffffffffu, vm, 2));
            float mn = fmaxf(m[r], vm);
            float corr = __expf(m[r] - mn);
            m[r] = mn;
            float ls = 0.f;
            #pragma unroll
            for (int nt = 0; nt < 16; ++nt) {
                float e0 = __expf(s_fr[nt][r * 2] - mn);
                float e1 = __expf(s_fr[nt][r * 2 + 1] - mn);
                s_fr[nt][r * 2] = e0;
                s_fr[nt][r * 2 + 1] = e1;
                ls += e0 + e1;
            }
            ls += __shfl_xor_sync(0xffffffffu, ls, 1);
            ls += __shfl_xor_sync(0xffffffffu, ls, 2);
            l[r] = l[r] * corr + ls;
            #pragma unroll
            for (int dn = 0; dn < 2; ++dn) {
                acc_o[dn][r * 2] *= corr;
                acc_o[dn][r * 2 + 1] *= corr;
            }
        }

        #pragma unroll
        for (int nt = 0; nt < 16; ++nt) {
            uint32_t pa[4];
            pa[0] = __float_as_uint(s_fr[nt][0]);
            pa[1] = __float_as_uint(s_fr[nt][2]);
            pa[2] = __float_as_uint(s_fr[nt][1]);
            pa[3] = __float_as_uint(s_fr[nt][3]);
            #pragma unroll
            for (int dn = 0; dn < 2; ++dn) {
                uint32_t bfr[2];
                bfr[0] = __float_as_uint(v_s[(nt * 8 + t) * 24 + dn * 8 + g]);
                bfr[1] = __float_as_uint(v_s[(nt * 8 + t + 4) * 24 + dn * 8 + g]);
                mma_tf32(acc_o[dn], pa, bfr);
            }
        }
    }

    #pragma unroll
    for (int r = 0; r < 2; ++r) {
        float inv = 1.f / l[r];
        int pos = q0 + wid * 16 + g + r * 8;
        int py = pos / 48, px = pos - py * 48;
        #pragma unroll
        for (int dn = 0; dn < 2; ++dn)
            #pragma unroll
            for (int cc2 = 0; cc2 < 2; ++cc2) {
                int d = dn * 8 + 2 * t + cc2;
                pad2[((size_t)b * 16 + d) * 2600 + (py + 1) * 50 + (px + 1)] =
                    acc_o[dn][r * 2 + cc2] * inv;
            }
    }
}

// ---------------- launcher ----------------
extern "C" void kernel_launch(void* const* d_in, const int* in_sizes, int n_in,
                              void* d_out, int out_size) {
    const float* x       = (const float*)d_in[0];
    const float* xe      = (const float*)d_in[1];
    const float* temb    = (const float*)d_in[2];
    const float* gn1_w   = (const float*)d_in[3];
    const float* gn1_b   = (const float*)d_in[4];
    const float* conv1_w = (const float*)d_in[5];
    const float* conv1_b = (const float*)d_in[6];
    const float* aff_w   = (const float*)d_in[7];
    const float* aff_b   = (const float*)d_in[8];
    const float* gn2_w   = (const float*)d_in[9];
    const float* gn2_b   = (const float*)d_in[10];
    const float* conv2_w = (const float*)d_in[11];
    const float* conv2_b = (const float*)d_in[12];
    const float* q_w     = (const float*)d_in[13];
    const float* kv_w    = (const float*)d_in[14];
    const float* out_w   = (const float*)d_in[15];
    const float* out_b   = (const float*)d_in[16];

    float *padp, *pad2p, *wtp, *wtBp, *wt2p, *h, *xres, *qb, *kvb;
    float *mean, *rstd, *gsum, *gsq, *gbsum;
    cudaGetSymbolAddress((void**)&padp,  g_pad);
    cudaGetSymbolAddress((void**)&pad2p, g_pad2);
    cudaGetSymbolAddress((void**)&wtp,   g_wt);
    cudaGetSymbolAddress((void**)&wtBp,  g_wtB);
    cudaGetSymbolAddress((void**)&wt2p,  g_wt2);
    cudaGetSymbolAddress((void**)&h,     g_h);
    cudaGetSymbolAddress((void**)&xres,  g_xres);
    cudaGetSymbolAddress((void**)&qb,    g_q);
    cudaGetSymbolAddress((void**)&kvb,   g_kv);
    cudaGetSymbolAddress((void**)&mean,  g_mean);
    cudaGetSymbolAddress((void**)&rstd,  g_rstd);
    cudaGetSymbolAddress((void**)&gsum,  g_gsum);
    cudaGetSymbolAddress((void**)&gsq,   g_gsq);
    cudaGetSymbolAddress((void**)&gbsum, g_gbsum);

    const int DSM_C = (4 * WBUFSZ + 2 * IBUFSZ) * 4;   // 84992 bytes
    const int DSM_16 = 4 * STG * 4;                    // 176128 bytes
    const int DSM_11 = (32 * 192 + 16 * 128) * 4;      // 32768 bytes
    cudaFuncSetAttribute(conv_mma<0>, cudaFuncAttributeMaxDynamicSharedMemorySize, DSM_C);
    cudaFuncSetAttribute(conv_mma<1>, cudaFuncAttributeMaxDynamicSharedMemorySize, DSM_C);
    cudaFuncSetAttribute(conv_mma16, cudaFuncAttributeMaxDynamicSharedMemorySize, DSM_16);

    // 1: prep (affine + weight transposes + gn_stats(x) + zero accum)
    //    blocks: 8 + 1296 + 1296 + 108 + 256 + 1 = 2965
    prep_kernel<<<2965, 256>>>(temb, aff_w, aff_b, gbsum,
                               conv1_w, conv2_w, out_w, wtp, wtBp, wt2p,
                               x, mean, rstd, gsum, gsq);
    // 2
    gn_apply_pad<<<TOTAL / 256, 256>>>(x, mean, rstd, gn1_w, gn1_b, padp);
    // 3: conv1 (+ fused gn2 stats)
    conv_mma<0><<<dim3(18, BB), 256, DSM_C>>>(padp, wtp, conv1_b, gbsum, h, gsum, gsq);
    // 4
    gn_apply_pad_fused<<<TOTAL / 256, 256>>>(h, gsum, gsq, gn2_w, gn2_b, padp);
    // 5
    conv_mma<1><<<dim3(18, BB), 256, DSM_C>>>(padp, wtBp, conv2_b, x, xres, gsum, gsq);
    // 6: both 1x1 convs in one launch
    conv1x1_both<<<dim3(18, BB, 2), 128, DSM_11>>>(xres, q_w, qb, xe, kv_w, kvb);
    // 7
    attn_mma<<<dim3(18, BB), 256>>>(qb, kvb, pad2p);
    // 8
    conv_mma16<<<dim3(18, BB), 256, DSM_16>>>(pad2p, wt2p, out_b, xres, (float*)d_out);
}

// round 15
// speedup vs baseline: 1.1228x; 1.0263x over previous
#include <cuda_runtime.h>
#include <cstdint>
#include <math.h>

#define HH 48
#define WW 48
#define SP 2304
#define CC 192
#define BB 8
#define TOTAL 3538944

typedef unsigned long long u64;

// ---------------- scratch ----------------
// padded input: per-channel [50 rows][52 cols], data at rows 1..48, cols 4..51
__device__ float g_pad[BB*CC*2600];
__device__ float g_pad2[BB*16*2600];   // attn out, zero-bordered [52][50] layout (unchanged)
__device__ float g_wt[CC*1728];
__device__ float g_wtB[CC*1728];
__device__ float g_wt2[CC*160];
__device__ float g_h[TOTAL];
__device__ float g_xres[TOTAL];
__device__ float g_q[BB*16*SP];
__device__ float g_kv[BB*32*SP];
__device__ float g_mean[BB*32];
__device__ float g_rstd[BB*32];
__device__ float g_gsum[BB*32];
__device__ float g_gsq[BB*32];
__device__ float g_gbsum[BB*CC];

// ---------------- helpers ----------------
__device__ __forceinline__ float warp_red(float v) {
    #pragma unroll
    for (int o = 16; o > 0; o >>= 1) v += __shfl_down_sync(0xffffffffu, v, o);
    return v;
}
__device__ __forceinline__ uint32_t to_tf32(float f) {
    uint32_t r; asm("cvt.rna.tf32.f32 %0, %1;" : "=r"(r) : "f"(f)); return r;
}
__device__ __forceinline__ void mma_tf32(float c[4], const uint32_t a[4], const uint32_t b[2]) {
    asm volatile(
        "mma.sync.aligned.m16n8k8.row.col.f32.tf32.tf32.f32 "
        "{%0,%1,%2,%3}, {%4,%5,%6,%7}, {%8,%9}, {%0,%1,%2,%3};"
        : "+f"(c[0]), "+f"(c[1]), "+f"(c[2]), "+f"(c[3])
        : "r"(a[0]), "r"(a[1]), "r"(a[2]), "r"(a[3]), "r"(b[0]), "r"(b[1]));
}
__device__ __forceinline__ void ldsm_x4(uint32_t r[4], uint32_t addr) {
    asm volatile("ldmatrix.sync.aligned.m8n8.x4.shared.b16 {%0,%1,%2,%3}, [%4];"
        : "=r"(r[0]), "=r"(r[1]), "=r"(r[2]), "=r"(r[3]) : "r"(addr));
}
__device__ __forceinline__ uint32_t smaddr(const void* p) {
    return (uint32_t)__cvta_generic_to_shared(p);
}
__device__ __forceinline__ void cp4(uint32_t dst, const void* src) {
    asm volatile("cp.async.ca.shared.global [%0], [%1], 4;" :: "r"(dst), "l"(src));
}
__device__ __forceinline__ void cp16(uint32_t dst, const void* src) {
    asm volatile("cp.async.cg.shared.global [%0], [%1], 16;" :: "r"(dst), "l"(src));
}
#define CP_COMMIT() asm volatile("cp.async.commit_group;" ::: "memory")
#define CP_WAIT2()  asm volatile("cp.async.wait_group 2;" ::: "memory")

// ---------------- prep: affine + weight transposes + gn_stats(x) + zero accum --------
__global__ __launch_bounds__(256) void prep_kernel(const float* __restrict__ temb,
                                                   const float* __restrict__ aw,
                                                   const float* __restrict__ ab,
                                                   float* __restrict__ gbsum,
                                                   const float* __restrict__ w1,
                                                   const float* __restrict__ w2,
                                                   const float* __restrict__ w3,
                                                   float* __restrict__ o1,
                                                   float* __restrict__ o2,
                                                   float* __restrict__ o3,
                                                   const float* __restrict__ x,
                                                   float* __restrict__ mean,
                                                   float* __restrict__ rstd,
                                                   float* __restrict__ gsum,
                                                   float* __restrict__ gsq) {
    int bx = blockIdx.x;
    int tid = threadIdx.x;
    if (bx < 8) {
        if (tid < 192) {
            __shared__ float t[192];
            t[tid] = temb[bx * 192 + tid];
            __syncthreads();
            float s = ab[tid] + ab[192 + tid];
            const float* wa = aw + tid * 192;
            const float* wb = aw + (192 + tid) * 192;
            for (int e = 0; e < 192; ++e) s = fmaf(t[e], wa[e] + wb[e], s);
            gbsum[bx * 192 + tid] = 0.5f * s;
        } else {
            __syncthreads();
        }
    } else if (bx < 8 + 1296) {
        // output-indexed: coalesced writes, strided reads
        int i = (bx - 8) * 256 + tid;
        if (i < CC * 1728) {
            int n = i / 1728;
            int r = i - n * 1728;
            int tap = r / 192;
            int ci = r - tap * 192;
            o1[i] = w1[n * 1728 + ci * 9 + tap];
        }
    } else if (bx < 8 + 2592) {
        int i = (bx - 8 - 1296) * 256 + tid;
        if (i < CC * 1728) {
            int n = i / 1728;
            int r = i - n * 1728;
            int tap = r / 192;
            int ci = r - tap * 192;
            o2[i] = w2[n * 1728 + ci * 9 + tap];
        }
    } else if (bx < 8 + 2592 + 120) {
        int i = (bx - 8 - 2592) * 256 + tid;
        if (i < CC * 160) {
            int n = i / 160;
            int r = i - n * 160;
            int tap = r / 16;
            int ci = r - tap * 16;
            o3[i] = (tap < 9) ? w3[n * 144 + ci * 9 + tap] : 0.f;
        }
    } else if (bx < 8 + 2592 + 120 + 256) {
        int bg = bx - 2720;
        const float* base = x + (long)bg * 13824;
        float s = 0.f, s2 = 0.f;
        for (int i = tid; i < 13824; i += 256) {
            float v = base[i];
            s += v; s2 = fmaf(v, v, s2);
        }
        __shared__ float shs[8], shs2[8];
        int w = tid >> 5, l = tid & 31;
        s = warp_red(s); s2 = warp_red(s2);
        if (l == 0) { shs[w] = s; shs2[w] = s2; }
        __syncthreads();
        if (w == 0) {
            s  = (l < 8) ? shs[l]  : 0.f;
            s2 = (l < 8) ? shs2[l] : 0.f;
            s = warp_red(s); s2 = warp_red(s2);
            if (l == 0) {
                float m = s * (1.f / 13824.f);
                float var = s2 * (1.f / 13824.f) - m * m;
                mean[bg] = m;
                rstd[bg] = rsqrtf(var + 1e-5f);
            }
        }
    } else {
        gsum[tid] = 0.f;
        gsq[tid] = 0.f;
    }
}

// ---------------- GroupNorm apply + swish -> padded (float4 vectorized) ------------
__global__ __launch_bounds__(256) void gn_apply_pad(const float* __restrict__ in,
                                                    const float* __restrict__ mean,
                                                    const float* __restrict__ rstd,
                                                    const float* __restrict__ w,
                                                    const float* __restrict__ bb,
                                                    float* __restrict__ outpad) {
    int i4 = blockIdx.x * 256 + threadIdx.x;   // 884736 threads
    int idx = i4 * 4;
    int bc = idx / SP;
    int sp = idx - bc * SP;
    int b = bc / CC;
    int c = bc - b * CC;
    int sidx = b * 32 + c / 6;
    float mn = __ldg(&mean[sidx]);
    float rs = __ldg(&rstd[sidx]);
    float ww = w[c], bv = bb[c];
    float4 v = *(const float4*)(in + idx);
    float4 o;
    float y;
    y = (v.x - mn) * rs * ww + bv; o.x = y / (1.f + __expf(-y));
    y = (v.y - mn) * rs * ww + bv; o.y = y / (1.f + __expf(-y));
    y = (v.z - mn) * rs * ww + bv; o.z = y / (1.f + __expf(-y));
    y = (v.w - mn) * rs * ww + bv; o.w = y / (1.f + __expf(-y));
    int py = sp / 48, px = sp - py * 48;
    *(float4*)(outpad + (size_t)bc * 2600 + (py + 1) * 52 + px + 4) = o;
}

__global__ __launch_bounds__(256) void gn_apply_pad_fused(const float* __restrict__ in,
                                                          const float* __restrict__ gsum,
                                                          const float* __restrict__ gsq,
                                                          const float* __restrict__ w,
                                                          const float* __restrict__ bb,
                                                          float* __restrict__ outpad) {
    int i4 = blockIdx.x * 256 + threadIdx.x;
    int idx = i4 * 4;
    int bc = idx / SP;
    int sp = idx - bc * SP;
    int b = bc / CC;
    int c = bc - b * CC;
    int sidx = b * 32 + c / 6;
    float s = __ldg(&gsum[sidx]);
    float s2 = __ldg(&gsq[sidx]);
    float mn = s * (1.f / 13824.f);
    float rs = rsqrtf(s2 * (1.f / 13824.f) - mn * mn + 1e-5f);
    float ww = w[c], bv = bb[c];
    float4 v = *(const float4*)(in + idx);
    float4 o;
    float y;
    y = (v.x - mn) * rs * ww + bv; o.x = y / (1.f + __expf(-y));
    y = (v.y - mn) * rs * ww + bv; o.y = y / (1.f + __expf(-y));
    y = (v.z - mn) * rs * ww + bv; o.z = y / (1.f + __expf(-y));
    y = (v.w - mn) * rs * ww + bv; o.w = y / (1.f + __expf(-y));
    int py = sp / 48, px = sp - py * 48;
    *(float4*)(outpad + (size_t)bc * 2600 + (py + 1) * 52 + px + 4) = o;
}

// ---------------- direct-shift TF32 mma conv (CIN=192, OC=192) --------------------
// R10 body EXACT; pad layout re-based to stride-52/col-offset-4 (tile contents
// bit-identical). EPI 0 adds R8-verified gn2 stats accumulation.
#define WROW 20
#define WBUFSZ (192 * WROW)
#define IBUFSZ (16 * 184)
#define IOFF (4 * WBUFSZ)
template<int EPI>
__global__ __launch_bounds__(256) void conv_mma(const float* __restrict__ pad,
                                                const float* __restrict__ wt,
                                                const float* __restrict__ bias,
                                                const float* __restrict__ extra,
                                                float* __restrict__ out,
                                                float* __restrict__ gsum,
                                                float* __restrict__ gsq) {
    extern __shared__ float sm[];

    const int mtile = blockIdx.x;
    const int b = blockIdx.y;
    const int tr = mtile / 3;
    const int tcl = mtile - tr * 3;
    const int tid = threadIdx.x;
    const int wid = tid >> 5;
    const int lane = tid & 31;
    const int g = lane >> 2;
    const int t = lane & 3;
    const int wm = wid & 3;
    const int wn = wid >> 2;

    const float* padb = pad + (size_t)b * CC * 2600;

    const uint32_t lane_a_off =
        ((uint32_t)((wm * 48 + (lane & 15)) * WROW + ((lane >> 4) << 2))) << 2;

    auto stage = [&](int s) {
        int c = s / 9;
        int tap = s - c * 9;
        float* wbuf = sm + (s & 3) * WBUFSZ;
        #pragma unroll
        for (int it = 0; it < 3; ++it) {
            int idx = it * 256 + tid;
            int n = idx >> 2;
            int kq = (idx & 3) * 4;
            cp16(smaddr(&wbuf[n * WROW + kq]),
                 wt + (size_t)n * 1728 + tap * 192 + c * 16 + kq);
        }
        if (tap == 0) {
            float* ibuf = sm + IOFF + (c & 1) * IBUFSZ;
            #pragma unroll
            for (int it = 0; it < 12; ++it) {
                int idx = it * 256 + tid;
                if (idx < 2880) {
                    int ci = idx / 180;
                    int rem = idx - ci * 180;
                    int rr = rem / 18;
                    int cc2 = rem - rr * 18;
                    cp4(smaddr(&ibuf[ci * 184 + rr * 18 + cc2]),
                        padb + (size_t)(c * 16 + ci) * 2600
                             + (tr * 8 + rr) * 52 + tcl * 16 + cc2 + 3);
                }
            }
        }
    };

    stage(0); CP_COMMIT();
    stage(1); CP_COMMIT();
    stage(2); CP_COMMIT();

    float acc[3][8][4];
    #pragma unroll
    for (int i = 0; i < 3; ++i)
        #pragma unroll
        for (int j = 0; j < 8; ++j)
            #pragma unroll
            for (int q = 0; q < 4; ++q) acc[i][j][q] = 0.f;

    for (int s = 0; s < 108; ++s) {
        CP_WAIT2();
        __syncthreads();
        const int c = s / 9;
        const int tap = s - c * 9;
        const int dy = tap / 3;
        const int dx = tap - dy * 3;
        const uint32_t wb_addr = smaddr(sm + (s & 3) * WBUFSZ) + lane_a_off;
        const float* ib = sm + IOFF + (c & 1) * IBUFSZ
                        + dy * 18 + dx + t * 184 + wn * 72 + g;
        #pragma unroll
        for (int ks = 0; ks < 2; ++ks) {
            const float* ibk = ib + ks * (8 * 184);
            uint32_t afr[3][4];
            #pragma unroll
            for (int i = 0; i < 3; ++i)
                ldsm_x4(afr[i], wb_addr + i * (16 * WROW * 4) + ks * 32);
            uint32_t bfr[8][2];
            #pragma unroll
            for (int j = 0; j < 8; ++j) {
                const float* a = ibk + (j >> 1) * 18 + (j & 1) * 8;
                bfr[j][0] = *(const uint32_t*)a;
                bfr[j][1] = *(const uint32_t*)(a + 4 * 184);
            }
            #pragma unroll
            for (int i = 0; i < 3; ++i)
                #pragma unroll
                for (int j = 0; j < 8; ++j)
                    mma_tf32(acc[i][j], afr[i], bfr[j]);
        }
        if (s + 3 < 108) stage(s + 3);
        CP_COMMIT();
    }

    __shared__ float sgs[32], sgq[32];
    if (EPI == 0) {
        if (tid < 32) { sgs[tid] = 0.f; sgq[tid] = 0.f; }
        __syncthreads();
    }
    #pragma unroll
    for (int i = 0; i < 3; ++i) {
        const int ch0 = wm * 48 + i * 16 + g;
        const int ch1 = ch0 + 8;
        const float bv0 = bias[ch0], bv1 = bias[ch1];
        float ga0 = 0.f, ga1 = 0.f;
        if (EPI == 0) { ga0 = extra[b * CC + ch0]; ga1 = extra[b * CC + ch1]; }
        float ps0 = 0.f, pq0 = 0.f, ps1 = 0.f, pq1 = 0.f;
        #pragma unroll
        for (int j = 0; j < 8; ++j) {
            const int n = wn * 64 + j * 8 + 2 * t;
            const int yy = tr * 8 + (n >> 4);
            const int xx = tcl * 16 + (n & 15);
            long idx0 = (((long)b * CC + ch0) * 48 + yy) * 48 + xx;
            long idx1 = (((long)b * CC + ch1) * 48 + yy) * 48 + xx;
            float y0 = acc[i][j][0] + bv0;
            float y1 = acc[i][j][1] + bv0;
            float y2 = acc[i][j][2] + bv1;
            float y3 = acc[i][j][3] + bv1;
            if (EPI == 0) {
                y0 += ga0 * y0 + ga0; y1 += ga0 * y1 + ga0;
                y2 += ga1 * y2 + ga1; y3 += ga1 * y3 + ga1;
                ps0 += y0 + y1; pq0 += y0 * y0 + y1 * y1;
                ps1 += y2 + y3; pq1 += y2 * y2 + y3 * y3;
            } else {
                float2 e0 = *(const float2*)(extra + idx0);
                float2 e1 = *(const float2*)(extra + idx1);
                y0 += e0.x; y1 += e0.y; y2 += e1.x; y3 += e1.y;
            }
            *(float2*)(out + idx0) = make_float2(y0, y1);
            *(float2*)(out + idx1) = make_float2(y2, y3);
        }
        if (EPI == 0) {
            ps0 += __shfl_xor_sync(0xffffffffu, ps0, 1);
            ps0 += __shfl_xor_sync(0xffffffffu, ps0, 2);
            pq0 += __shfl_xor_sync(0xffffffffu, pq0, 1);
            pq0 += __shfl_xor_sync(0xffffffffu, pq0, 2);
            ps1 += __shfl_xor_sync(0xffffffffu, ps1, 1);
            ps1 += __shfl_xor_sync(0xffffffffu, ps1, 2);
            pq1 += __shfl_xor_sync(0xffffffffu, pq1, 1);
            pq1 += __shfl_xor_sync(0xffffffffu, pq1, 2);
            if (t == 0) {
                atomicAdd(&sgs[ch0 / 6], ps0);
                atomicAdd(&sgq[ch0 / 6], pq0);
                atomicAdd(&sgs[ch1 / 6], ps1);
                atomicAdd(&sgq[ch1 / 6], pq1);
            }
        }
    }
    if (EPI == 0) {
        __syncthreads();
        if (tid < 32) {
            atomicAdd(&gsum[b * 32 + tid], sgs[tid]);
            atomicAdd(&gsq[b * 32 + tid], sgq[tid]);
        }
    }
}

// ---------------- out conv: CIN=16 (K padded to 160), im2col pipeline ----------------
#define WST 36
#define ASZ (192 * WST)
#define BSZ (32 * 128)
#define STG (ASZ + BSZ)
__global__ __launch_bounds__(256) void conv_mma16(const float* __restrict__ pad2,
                                                  const float* __restrict__ wt,
                                                  const float* __restrict__ bias,
                                                  const float* __restrict__ extra,
                                                  float* __restrict__ out) {
    extern __shared__ float smf[];
    uint32_t* sm = (uint32_t*)smf;

    const int mtile = blockIdx.x;
    const int b = blockIdx.y;
    const int tid = threadIdx.x;
    const int wid = tid >> 5;
    const int lane = tid & 31;
    const int g = lane >> 2;
    const int t = lane & 3;
    const int wm = wid & 3;
    const int wn = wid >> 2;

    const int p = tid & 127;
    const int khalf = tid >> 7;
    const int pg = mtile * 128 + p;
    const int py = pg / 48;
    const int px = pg - py * 48;
    const float* padb = pad2 + (size_t)b * 16 * 2600;

    auto stage = [&](int c) {
        uint32_t* buf = sm + (c & 3) * STG;
        const int tap = 2 * c + khalf;
        const int dy = tap / 3;
        const int dx = tap - dy * 3;
        const float* bsrc = padb + (py + dy) * 50 + (px + dx);
        uint32_t* Bs = buf + ASZ;
        #pragma unroll
        for (int i = 0; i < 16; ++i) {
            int kk = khalf * 16 + i;
            cp4(smaddr(&Bs[kk * 128 + (p ^ ((kk & 3) * 8))]), bsrc + (size_t)i * 2600);
        }
        #pragma unroll
        for (int it = 0; it < 6; ++it) {
            int idx = it * 256 + tid;
            int n = idx >> 3;
            int kq = (idx & 7) * 4;
            cp16(smaddr(&buf[n * WST + kq]), wt + (size_t)n * 160 + c * 32 + kq);
        }
    };

    stage(0); CP_COMMIT();
    stage(1); CP_COMMIT();
    stage(2); CP_COMMIT();

    float acc[3][8][4];
    #pragma unroll
    for (int i = 0; i < 3; ++i)
        #pragma unroll
        for (int j = 0; j < 8; ++j)
            #pragma unroll
            for (int q = 0; q < 4; ++q) acc[i][j][q] = 0.f;

    for (int c = 0; c < 5; ++c) {
        CP_WAIT2();
        __syncthreads();
        const uint32_t* Wp = sm + (c & 3) * STG;
        const uint32_t* Ip = Wp + ASZ;
        #pragma unroll
        for (int ks = 0; ks < 4; ++ks) {
            const int kk0 = ks * 8;
            uint32_t afr[3][4];
            #pragma unroll
            for (int i = 0; i < 3; ++i) {
                int row = wm * 48 + i * 16 + g;
                afr[i][0] = Wp[row * WST + kk0 + t];
                afr[i][1] = Wp[(row + 8) * WST + kk0 + t];
                afr[i][2] = Wp[row * WST + kk0 + t + 4];
                afr[i][3] = Wp[(row + 8) * WST + kk0 + t + 4];
            }
            uint32_t bfr[8][2];
            #pragma unroll
            for (int j = 0; j < 8; ++j) {
                int pp = wn * 64 + j * 8 + g;
                int ppx = pp ^ (t * 8);
                bfr[j][0] = Ip[(kk0 + t) * 128 + ppx];
                bfr[j][1] = Ip[(kk0 + t + 4) * 128 + ppx];
            }
            #pragma unroll
            for (int i = 0; i < 3; ++i)
                #pragma unroll
                for (int j = 0; j < 8; ++j)
                    mma_tf32(acc[i][j], afr[i], bfr[j]);
        }
        if (c + 3 < 5) stage(c + 3);
        CP_COMMIT();
    }

    #pragma unroll
    for (int i = 0; i < 3; ++i) {
        const int ch0 = wm * 48 + i * 16 + g;
        const int ch1 = ch0 + 8;
        const float bv0 = bias[ch0], bv1 = bias[ch1];
        #pragma unroll
        for (int j = 0; j < 8; ++j) {
            const int pos = mtile * 128 + wn * 64 + j * 8 + 2 * t;
            long idx0 = ((long)b * CC + ch0) * SP + pos;
            long idx1 = ((long)b * CC + ch1) * SP + pos;
            float2 e0 = *(const float2*)(extra + idx0);
            float2 e1 = *(const float2*)(extra + idx1);
            *(float2*)(out + idx0) = make_float2(acc[i][j][0] + bv0 + e0.x,
                                                 acc[i][j][1] + bv0 + e0.y);
            *(float2*)(out + idx1) = make_float2(acc[i][j][2] + bv1 + e1.x,
                                                 acc[i][j][3] + bv1 + e1.y);
        }
    }
}

// ---------------- merged 1x1 convs: z=0 -> q (CO=16), z=1 -> kv (CO=32) --------------
template<int CO>
__device__ __forceinline__ void conv1x1_body(const float* __restrict__ in,
                                             const float* __restrict__ wgt,
                                             float* __restrict__ out,
                                             float* s_w, float* s_x,
                                             int b, int p0, int tid) {
    for (int i = tid; i < CO * 192; i += 128) s_w[i] = wgt[i];
    float acc[CO];
    #pragma unroll
    for (int co = 0; co < CO; ++co) acc[co] = 0.f;

    for (int c0 = 0; c0 < 192; c0 += 16) {
        __syncthreads();
        for (int i = tid; i < 16 * 128; i += 128) {
            int ci = i >> 7;
            int pp = i & 127;
            s_x[i] = in[((long)b * 192 + c0 + ci) * SP + p0 + pp];
        }
        __syncthreads();
        #pragma unroll
        for (int ci = 0; ci < 16; ++ci) {
            float xv = s_x[ci * 128 + tid];
            #pragma unroll
            for (int co = 0; co < CO; ++co)
                acc[co] = fmaf(s_w[co * 192 + c0 + ci], xv, acc[co]);
        }
    }
    #pragma unroll
    for (int co = 0; co < CO; ++co)
        out[((long)b * CO + co) * SP + p0 + tid] = acc[co];
}

__global__ __launch_bounds__(128) void conv1x1_both(const float* __restrict__ xres,
                                                    const float* __restrict__ q_w,
                                                    float* __restrict__ qb,
                                                    const float* __restrict__ xe,
                                                    const float* __restrict__ kv_w,
                                                    float* __restrict__ kvb) {
    extern __shared__ float smem[];
    float* s_w = smem;
    float* s_x = smem + 32 * 192;
    const int b = blockIdx.y;
    const int p0 = blockIdx.x * 128;
    const int tid = threadIdx.x;
    if (blockIdx.z == 0)
        conv1x1_body<16>(xres, q_w, qb, s_w, s_x, b, p0, tid);
    else
        conv1x1_body<32>(xe, kv_w, kvb, s_w, s_x, b, p0, tid);
}

// ---------------- MMA flash attention -> padded [b][16][52][50] ----------------
__global__ __launch_bounds__(256) void attn_mma(const float* __restrict__ q,
                                                const float* __restrict__ kv,
                                                float* __restrict__ pad2) {
    const int b = blockIdx.y;
    const int mtile = blockIdx.x;
    const int q0 = mtile * 128;
    const int tid = threadIdx.x;
    const int wid = tid >> 5;
    const int lane = tid & 31;
    const int g = lane >> 2;
    const int t = lane & 3;

    __shared__ float k_s[16 * 136];
    __shared__ float v_s[128 * 24];

    uint32_t qa[2][4];
    #pragma unroll
    for (int kd = 0; kd < 2; ++kd)
        #pragma unroll
        for (int j = 0; j < 4; ++j) {
            int row = wid * 16 + g + (j & 1) * 8;
            int d = kd * 8 + t + (j >> 1) * 4;
            float v = q[((long)b * 16 + d) * SP + q0 + row] * 0.25f;
            qa[kd][j] = to_tf32(v);
        }

    float m[2] = { -3.4e38f, -3.4e38f };
    float l[2] = { 0.f, 0.f };
    float acc_o[2][4];
    #pragma unroll
    for (int dn = 0; dn < 2; ++dn)
        #pragma unroll
        for (int j = 0; j < 4; ++j) acc_o[dn][j] = 0.f;

    const long kvb = (long)b * 32 * SP;
    for (int kb = 0; kb < 18; ++kb) {
        __syncthreads();
        const int key0 = kb * 128;
        #pragma unroll
        for (int it = 0; it < 8; ++it) {
            int idx = it * 256 + tid;
            int c = idx >> 7;
            int key = idx & 127;
            k_s[c * 136 + key] =
                __uint_as_float(to_tf32(kv[kvb + (long)c * SP + key0 + key]));
        }
        #pragma unroll
        for (int it = 0; it < 8; ++it) {
            int idx = it * 256 + tid;
            int d = idx >> 7;
            int key = idx & 127;
            int kp = key & 7;
            int kap = (kp & 1) ? (kp >> 1) + 4 : (kp >> 1);
            int slot = (key & ~7) | kap;
            v_s[slot * 24 + d] =
                __uint_as_float(to_tf32(kv[kvb + (long)(16 + d) * SP + key0 + key]));
        }
        __syncthreads();

        float s_fr[16][4];
        #pragma unroll
        for (int nt = 0; nt < 16; ++nt) {
            float c4[4] = { 0.f, 0.f, 0.f, 0.f };
            #pragma unroll
            for (int kd = 0; kd < 2; ++kd) {
                uint32_t bfr[2];
                bfr[0] = __float_as_uint(k_s[(kd * 8 + t) * 136 + nt * 8 + g]);
                bfr[1] = __float_as_uint(k_s[(kd * 8 + t + 4) * 136 + nt * 8 + g]);
                mma_tf32(c4, qa[kd], bfr);
            }
            s_fr[nt][0] = c4[0]; s_fr[nt][1] = c4[1];
            s_fr[nt][2] = c4[2]; s_fr[nt][3] = c4[3];
        }

        #pragma unroll
        for (int r = 0; r < 2; ++r) {
            float vm = -3.4e38f;
            #pragma unroll
            for (int nt = 0; nt < 16; ++nt)
                vm = fmaxf(vm, fmaxf(s_fr[nt][r * 2], s_fr[nt][r * 2 + 1]));
            vm = fmaxf(vm, __shfl_xor_sync(0xffffffffu, vm, 1));
            vm = fmaxf(vm, __shfl_xor_sync(0xffffffffu, vm, 2));
            float mn = fmaxf(m[r], vm);
            float corr = __expf(m[r] - mn);
            m[r] = mn;
            float ls = 0.f;
            #pragma unroll
            for (int nt = 0; nt < 16; ++nt) {
                float e0 = __expf(s_fr[nt][r * 2] - mn);
                float e1 = __expf(s_fr[nt][r * 2 + 1] - mn);
                s_fr[nt][r * 2] = e0;
                s_fr[nt][r * 2 + 1] = e1;
                ls += e0 + e1;
            }
            ls += __shfl_xor_sync(0xffffffffu, ls, 1);
            ls += __shfl_xor_sync(0xffffffffu, ls, 2);
            l[r] = l[r] * corr + ls;
            #pragma unroll
            for (int dn = 0; dn < 2; ++dn) {
                acc_o[dn][r * 2] *= corr;
                acc_o[dn][r * 2 + 1] *= corr;
            }
        }

        #pragma unroll
        for (int nt = 0; nt < 16; ++nt) {
            uint32_t pa[4];
            pa[0] = __float_as_uint(s_fr[nt][0]);
            pa[1] = __float_as_uint(s_fr[nt][2]);
            pa[2] = __float_as_uint(s_fr[nt][1]);
            pa[3] = __float_as_uint(s_fr[nt][3]);
            #pragma unroll
            for (int dn = 0; dn < 2; ++dn) {
                uint32_t bfr[2];
                bfr[0] = __float_as_uint(v_s[(nt * 8 + t) * 24 + dn * 8 + g]);
                bfr[1] = __float_as_uint(v_s[(nt * 8 + t + 4) * 24 + dn * 8 + g]);
                mma_tf32(acc_o[dn], pa, bfr);
            }
        }
    }

    #pragma unroll
    for (int r = 0; r < 2; ++r) {
        float inv = 1.f / l[r];
        int pos = q0 + wid * 16 + g + r * 8;
        int py = pos / 48, px = pos - py * 48;
        #pragma unroll
        for (int dn = 0; dn < 2; ++dn)
            #pragma unroll
            for (int cc2 = 0; cc2 < 2; ++cc2) {
                int d = dn * 8 + 2 * t + cc2;
                pad2[((size_t)b * 16 + d) * 2600 + (py + 1) * 50 + (px + 1)] =
                    acc_o[dn][r * 2 + cc2] * inv;
            }
    }
}

// ---------------- launcher ----------------
extern "C" void kernel_launch(void* const* d_in, const int* in_sizes, int n_in,
                              void* d_out, int out_size) {
    const float* x       = (const float*)d_in[0];
    const float* xe      = (const float*)d_in[1];
    const float* temb    = (const float*)d_in[2];
    const float* gn1_w   = (const float*)d_in[3];
    const float* gn1_b   = (const float*)d_in[4];
    const float* conv1_w = (const float*)d_in[5];
    const float* conv1_b = (const float*)d_in[6];
    const float* aff_w   = (const float*)d_in[7];
    const float* aff_b   = (const float*)d_in[8];
    const float* gn2_w   = (const float*)d_in[9];
    const float* gn2_b   = (const float*)d_in[10];
    const float* conv2_w = (const float*)d_in[11];
    const float* conv2_b = (const float*)d_in[12];
    const float* q_w     = (const float*)d_in[13];
    const float* kv_w    = (const float*)d_in[14];
    const float* out_w   = (const float*)d_in[15];
    const float* out_b   = (const float*)d_in[16];

    float *padp, *pad2p, *wtp, *wtBp, *wt2p, *h, *xres, *qb, *kvb;
    float *mean, *rstd, *gsum, *gsq, *gbsum;
    cudaGetSymbolAddress((void**)&padp,  g_pad);
    cudaGetSymbolAddress((void**)&pad2p, g_pad2);
    cudaGetSymbolAddress((void**)&wtp,   g_wt);
    cudaGetSymbolAddress((void**)&wtBp,  g_wtB);
    cudaGetSymbolAddress((void**)&wt2p,  g_wt2);
    cudaGetSymbolAddress((void**)&h,     g_h);
    cudaGetSymbolAddress((void**)&xres,  g_xres);
    cudaGetSymbolAddress((void**)&qb,    g_q);
    cudaGetSymbolAddress((void**)&kvb,   g_kv);
    cudaGetSymbolAddress((void**)&mean,  g_mean);
    cudaGetSymbolAddress((void**)&rstd,  g_rstd);
    cudaGetSymbolAddress((void**)&gsum,  g_gsum);
    cudaGetSymbolAddress((void**)&gsq,   g_gsq);
    cudaGetSymbolAddress((void**)&gbsum, g_gbsum);

    const int DSM_C = (4 * WBUFSZ + 2 * IBUFSZ) * 4;   // 84992 bytes
    const int DSM_16 = 4 * STG * 4;                    // 176128 bytes
    const int DSM_11 = (32 * 192 + 16 * 128) * 4;      // 32768 bytes
    cudaFuncSetAttribute(conv_mma<0>, cudaFuncAttributeMaxDynamicSharedMemorySize, DSM_C);
    cudaFuncSetAttribute(conv_mma<1>, cudaFuncAttributeMaxDynamicSharedMemorySize, DSM_C);
    cudaFuncSetAttribute(conv_mma16, cudaFuncAttributeMaxDynamicSharedMemorySize, DSM_16);

    // 1: prep — blocks: 8 + 1296 + 1296 + 120 + 256 + 1 = 2977
    prep_kernel<<<2977, 256>>>(temb, aff_w, aff_b, gbsum,
                               conv1_w, conv2_w, out_w, wtp, wtBp, wt2p,
                               x, mean, rstd, gsum, gsq);
    // 2
    gn_apply_pad<<<TOTAL / 1024, 256>>>(x, mean, rstd, gn1_w, gn1_b, padp);
    // 3: conv1 (+ fused gn2 stats)
    conv_mma<0><<<dim3(18, BB), 256, DSM_C>>>(padp, wtp, conv1_b, gbsum, h, gsum, gsq);
    // 4
    gn_apply_pad_fused<<<TOTAL / 1024, 256>>>(h, gsum, gsq, gn2_w, gn2_b, padp);
    // 5
    conv_mma<1><<<dim3(18, BB), 256, DSM_C>>>(padp, wtBp, conv2_b, x, xres, gsum, gsq);
    // 6
    conv1x1_both<<<dim3(18, BB, 2), 128, DSM_11>>>(xres, q_w, qb, xe, kv_w, kvb);
    // 7
    attn_mma<<<dim3(18, BB), 256>>>(qb, kvb, pad2p);
    // 8
    conv_mma16<<<dim3(18, BB), 256, DSM_16>>>(pad2p, wt2p, out_b, xres, (float*)d_out);
}